// round 6
// baseline (speedup 1.0000x reference)
#include <cuda_runtime.h>
#include <math.h>

#define BB   16
#define TT   8000
#define TN   800
#define HID  512
#define LAT  128
#define KCB  1024
#define NQ   4
#define COUNT_DEC 1599
#define NCHUNKS   25584   // BB * COUNT_DEC
#define RESCORE_TAU 4e-3f

typedef unsigned long long ull;

// ---------------- f32x2 packed helpers (sm_103a FFMA2 path) ----------------
__device__ __forceinline__ ull fma2(ull a, ull b, ull c) {
    ull d;
    asm("fma.rn.f32x2 %0, %1, %2, %3;" : "=l"(d) : "l"(a), "l"(b), "l"(c));
    return d;
}
__device__ __forceinline__ ull add2(ull a, ull b) {
    ull d;
    asm("add.rn.f32x2 %0, %1, %2;" : "=l"(d) : "l"(a), "l"(b));
    return d;
}
__device__ __forceinline__ ull pack2(float lo, float hi) {
    ull d;
    asm("mov.b64 %0, {%1, %2};" : "=l"(d) : "f"(lo), "f"(hi));
    return d;
}
__device__ __forceinline__ float2 unpack2(ull a) {
    float lo, hi;
    asm("mov.b64 {%0, %1}, %2;" : "=f"(lo), "=f"(hi) : "l"(a));
    return make_float2(lo, hi);
}

// ---------------- scratch (device globals; no allocation allowed) ----------------
__device__ float g_z1[BB*HID*TN];        // enc1 out (B,512,800)
__device__ float g_z3[(size_t)BB*HID*TT];// enc2a out (B,512,8000)
__device__ float g_ze[(size_t)BB*TT*LAT];// enc2b out, transposed (B,T,128)
__device__ float g_res[(size_t)BB*TT*LAT];
__device__ float g_qout[(size_t)BB*TT*LAT];
__device__ int   g_codes[BB*TT*NQ];
__device__ float g_cbn[NQ*KCB];
__device__ float g_w1t[132*5*512];       // dec1 weights transposed: [(c*5+j)*512 + o]
__device__ float g_w2t[512*3*128];       // dec2 weights transposed: [(c*3+j)*128 + o]
__device__ double g_acc[8];  // [0..3] vq sums, [4] smooth count, [5] recon sum

// ---------------- tiny utility kernels ----------------
__global__ void k_zero_acc() {
    if (threadIdx.x < 8) g_acc[threadIdx.x] = 0.0;
}

__global__ void k_tw1(const float* __restrict__ w1) {
    int idx = blockIdx.x * 256 + threadIdx.x;
    if (idx >= 512*660) return;
    int o = idx / 660, r = idx % 660;
    g_w1t[r*512 + o] = w1[idx];     // r = c*5 + j already
}
__global__ void k_tw2(const float* __restrict__ w2) {
    int idx = blockIdx.x * 256 + threadIdx.x;
    if (idx >= 128*1536) return;
    int o = idx / 1536, r = idx % 1536;
    g_w2t[r*128 + o] = w2[idx];     // r = c*3 + j already
}

// ---------------- enc1: (B,20,800) -> relu conv K=3 -> (B,512,800) ----------------
__global__ __launch_bounds__(256) void k_enc1(const float* __restrict__ traj,
                                              const float* __restrict__ w,
                                              const float* __restrict__ bias) {
    __shared__ float xs[20][18];
    int b = blockIdx.y, t0 = blockIdx.x * 16;
    int tid = threadIdx.x;
    for (int e = tid; e < 20*18; e += 256) {
        int i = e / 18, u = e % 18;
        int tg = t0 + u - 1;
        float v = 0.f;
        if (tg >= 0 && tg < TN) v = traj[((size_t)b*2 + (i/10))*TT + tg*10 + (i%10)];
        xs[i][u] = v;
    }
    __syncthreads();
    int o0 = tid, o1 = tid + 256;
    float acc0[16], acc1[16];
    float b0 = bias[o0], b1v = bias[o1];
    #pragma unroll
    for (int t = 0; t < 16; t++) { acc0[t] = 0.f; acc1[t] = 0.f; }
    for (int i = 0; i < 20; i++) {
        #pragma unroll
        for (int j = 0; j < 3; j++) {
            float w0 = w[(o0*20 + i)*3 + j];
            float w1 = w[(o1*20 + i)*3 + j];
            #pragma unroll
            for (int t = 0; t < 16; t++) {
                float x = xs[i][t + j];
                acc0[t] += w0 * x;
                acc1[t] += w1 * x;
            }
        }
    }
    #pragma unroll
    for (int t = 0; t < 16; t++) {
        g_z1[((size_t)b*HID + o0)*TN + t0 + t] = fmaxf(acc0[t] + b0, 0.f);
        g_z1[((size_t)b*HID + o1)*TN + t0 + t] = fmaxf(acc1[t] + b1v, 0.f);
    }
}

// ---------------- conv v3: 64T x 128OC tile, thread = 4T x 8OC, FFMA2 ----------------
// Packing is over OC pairs: wsm float4 -> two f32x2 {w_c0,w_c1},{w_c2,w_c3}.
// Per-half accumulation order identical to the scalar version (bit-exact per OC).
template<int K, bool RELU, bool TROUT, bool INTERP>
__global__ __launch_bounds__(256) void k_conv2(const float* __restrict__ in,
                                               const float* __restrict__ wt,
                                               const float* __restrict__ bias,
                                               float* __restrict__ out) {
    constexpr int P   = (K - 1) / 2;
    constexpr int ZW  = 64 + K - 1;                    // 68 (K=5) / 70 (K=7)
    constexpr int ZWP = (ZW % 4 == 0) ? ZW : ZW + (4 - ZW % 4);  // 68 / 72
    constexpr int NZ4 = (K + 6) / 4;                   // 2 / 3
    constexpr int PW  = 132;                           // wsm pitch
    __shared__ float wsm[8 * K * PW];
    __shared__ float zsm[8 * ZWP];
    int tid = threadIdx.x;
    int tx = tid & 15, ty = tid >> 4;
    int t0 = blockIdx.x * 64, ob = blockIdx.y * 128, b = blockIdx.z;
    int OCt = gridDim.y * 128;
    int o = ob + ty * 8, tt = tx * 4;

    ull accp[4][4], sump[4][4];   // [oc-pair][tl]
    #pragma unroll
    for (int cp = 0; cp < 4; cp++)
        #pragma unroll
        for (int tl = 0; tl < 4; tl++) { accp[cp][tl] = 0ull; sump[cp][tl] = 0ull; }

    for (int chunk = 0; chunk < 64; chunk++) {
        int ic0 = chunk * 8;
        __syncthreads();
        // weights: contiguous global reads, strided smem writes (pitch 132)
        for (int e = tid; e < 8 * K * 128; e += 256) {
            int ol = e / (8 * K);
            int r  = e - ol * (8 * K);
            int i  = r / K, j = r - i * K;
            wsm[(i*K + j)*PW + ol] = wt[((size_t)(ob + ol)*512 + ic0 + i)*K + j];
        }
        // input tile
        for (int e = tid; e < 8 * ZW; e += 256) {
            int i = e / ZW, u = e - i * ZW;
            int tg = t0 + u - P;
            float v = 0.f;
            if (tg >= 0 && tg < TT) {
                if (INTERP) {
                    const float* row = g_z1 + ((size_t)b*HID + ic0 + i)*TN;
                    float src = fmaxf(((float)tg + 0.5f)*0.5f - 0.5f, 0.0f);
                    int i0 = (int)src;
                    int i1 = min(i0 + 1, 3999);
                    float frac = src - (float)i0;
                    float v0 = row[i0 / 5];
                    float v1 = row[i1 / 5];
                    v = v0 * (1.0f - frac) + v1 * frac;
                } else {
                    v = in[((size_t)b*HID + ic0 + i)*TT + tg];
                }
            }
            zsm[i*ZWP + u] = v;
        }
        __syncthreads();
        #pragma unroll
        for (int i = 0; i < 8; i++) {
            float zr[NZ4 * 4];
            #pragma unroll
            for (int q = 0; q < NZ4; q++)
                *(float4*)&zr[q*4] = *(const float4*)&zsm[i*ZWP + tt + q*4];
            ull zp[K + 3];
            #pragma unroll
            for (int u = 0; u < K + 3; u++) zp[u] = pack2(zr[u], zr[u]);
            #pragma unroll
            for (int j = 0; j < K; j++) {
                ulonglong2 wA = *(const ulonglong2*)&wsm[(i*K + j)*PW + ty*8];
                ulonglong2 wB = *(const ulonglong2*)&wsm[(i*K + j)*PW + ty*8 + 4];
                #pragma unroll
                for (int tl = 0; tl < 4; tl++) {
                    ull z = zp[tl + j];
                    accp[0][tl] = fma2(wA.x, z, accp[0][tl]);
                    accp[1][tl] = fma2(wA.y, z, accp[1][tl]);
                    accp[2][tl] = fma2(wB.x, z, accp[2][tl]);
                    accp[3][tl] = fma2(wB.y, z, accp[3][tl]);
                }
            }
        }
        if ((chunk & 3) == 3) {   // flush short fp32 chains
            #pragma unroll
            for (int cp = 0; cp < 4; cp++)
                #pragma unroll
                for (int tl = 0; tl < 4; tl++) { sump[cp][tl] = add2(sump[cp][tl], accp[cp][tl]); accp[cp][tl] = 0ull; }
        }
    }

    float resv[8][4];
    #pragma unroll
    for (int cp = 0; cp < 4; cp++) {
        float bv0 = bias[o + 2*cp], bv1 = bias[o + 2*cp + 1];
        #pragma unroll
        for (int tl = 0; tl < 4; tl++) {
            float2 s = unpack2(sump[cp][tl]);
            float v0 = s.x + bv0, v1 = s.y + bv1;
            if (RELU) { v0 = fmaxf(v0, 0.f); v1 = fmaxf(v1, 0.f); }
            resv[2*cp][tl] = v0; resv[2*cp + 1][tl] = v1;
        }
    }
    if (!TROUT) {
        #pragma unroll
        for (int c = 0; c < 8; c++) {
            float4 v = make_float4(resv[c][0], resv[c][1], resv[c][2], resv[c][3]);
            *(float4*)&out[((size_t)b*OCt + o + c)*TT + t0 + tt] = v;
        }
    } else {
        #pragma unroll
        for (int tl = 0; tl < 4; tl++) {
            float4 va = make_float4(resv[0][tl], resv[1][tl], resv[2][tl], resv[3][tl]);
            float4 vb = make_float4(resv[4][tl], resv[5][tl], resv[6][tl], resv[7][tl]);
            *(float4*)&out[((size_t)b*TT + t0 + tt + tl)*OCt + o]     = va;
            *(float4*)&out[((size_t)b*TT + t0 + tt + tl)*OCt + o + 4] = vb;
        }
    }
}

// ---------------- codebook squared norms (double, stored fp32) ----------------
__global__ void k_cbnorm(const float* __restrict__ cb) {
    int id = blockIdx.x * 256 + threadIdx.x;
    if (id >= NQ * KCB) return;
    const float* r = cb + (size_t)id * LAT;
    double s = 0.0;
    for (int d = 0; d < LAT; d++) {
        double v = (double)r[d];
        s += v * v;
    }
    g_cbn[id] = (float)s;
}

// ---------------- residual VQ, one codebook per launch (FFMA2 dot products) ----------------
__global__ __launch_bounds__(256) void k_vq(const float* __restrict__ cb_all, int qi) {
    extern __shared__ float sm[];
    float* rsm = sm;                      // 64 x 132
    float* csm = sm + 64*132;             // 128 x 132
    float* nsm = csm + 128*132;           // 128
    int tid = threadIdx.x, lane = tid & 31, w = tid >> 5;
    int row0 = blockIdx.x * 64;
    const float* src = (qi == 0) ? g_ze : g_res;
    for (int e = tid; e < 64*32; e += 256) {
        int lr = e >> 5, d4 = (e & 31) * 4;
        float4 v = *(const float4*)&src[(size_t)(row0 + lr)*LAT + d4];
        *(float4*)&rsm[lr*132 + d4] = v;
    }
    const float* cbq = cb_all + (size_t)qi * KCB * LAT;
    float bestv[8], secv[8]; int besti[8];
    #pragma unroll
    for (int rr = 0; rr < 8; rr++) { bestv[rr] = 3.4e38f; secv[rr] = 3.4e38f; besti[rr] = 0; }

    for (int cc = 0; cc < 8; cc++) {
        __syncthreads();
        for (int e = tid; e < 128*32; e += 256) {
            int k = e >> 5, d4 = (e & 31) * 4;
            float4 v = *(const float4*)&cbq[(size_t)(cc*128 + k)*LAT + d4];
            *(float4*)&csm[k*132 + d4] = v;
        }
        if (tid < 128) nsm[tid] = g_cbn[qi*KCB + cc*128 + tid];
        __syncthreads();
        ull accp[8][4];   // packed {even-sum, odd-sum}
        #pragma unroll
        for (int rr = 0; rr < 8; rr++)
            #pragma unroll
            for (int c = 0; c < 4; c++) accp[rr][c] = 0ull;
        #pragma unroll 2
        for (int d = 0; d < 128; d += 4) {
            ulonglong2 cv[4];
            #pragma unroll
            for (int c = 0; c < 4; c++) cv[c] = *(const ulonglong2*)&csm[(lane*4 + c)*132 + d];
            #pragma unroll
            for (int rr = 0; rr < 8; rr++) {
                ulonglong2 rv = *(const ulonglong2*)&rsm[(w*8 + rr)*132 + d];
                #pragma unroll
                for (int c = 0; c < 4; c++) {
                    accp[rr][c] = fma2(rv.x, cv[c].x, accp[rr][c]);
                    accp[rr][c] = fma2(rv.y, cv[c].y, accp[rr][c]);
                }
            }
        }
        #pragma unroll
        for (int rr = 0; rr < 8; rr++) {
            #pragma unroll
            for (int c = 0; c < 4; c++) {
                float2 h = unpack2(accp[rr][c]);
                float dist = nsm[lane*4 + c] - 2.0f * (h.x + h.y);
                int idx = cc*128 + lane*4 + c;
                if (dist < bestv[rr]) { secv[rr] = bestv[rr]; bestv[rr] = dist; besti[rr] = idx; }
                else if (dist < secv[rr]) { secv[rr] = dist; }
            }
        }
    }

    double dq_local = 0.0;
    for (int rr = 0; rr < 8; rr++) {
        float v1 = bestv[rr]; int i1 = besti[rr]; float v2 = secv[rr];
        #pragma unroll
        for (int off = 16; off > 0; off >>= 1) {
            float ov1 = __shfl_xor_sync(0xffffffffu, v1, off);
            int   oi1 = __shfl_xor_sync(0xffffffffu, i1, off);
            float ov2 = __shfl_xor_sync(0xffffffffu, v2, off);
            if (ov1 < v1 || (ov1 == v1 && oi1 < i1)) {
                v2 = fminf(v1, ov2);
                v1 = ov1; i1 = oi1;
            } else {
                v2 = fminf(v2, ov1);
            }
        }
        int ix = i1;
        int rloc = w*8 + rr;
        // ---- exact fp64 rescore when the fp32 margin is too small ----
        if (v2 - v1 < RESCORE_TAU) {
            double bd = 1e300; int bi = 0x7fffffff;
            for (int kk = 0; kk < 32; kk++) {
                int k = kk*32 + lane;
                const float* cr = cbq + (size_t)k * LAT;
                double s = 0.0;
                for (int d = 0; d < 128; d++) {
                    double cd = (double)cr[d];
                    double rd = (double)rsm[rloc*132 + d];
                    s += cd*cd - 2.0*rd*cd;
                }
                if (s < bd || (s == bd && k < bi)) { bd = s; bi = k; }
            }
            #pragma unroll
            for (int off = 16; off > 0; off >>= 1) {
                double ob = __shfl_xor_sync(0xffffffffu, bd, off);
                int    oi = __shfl_xor_sync(0xffffffffu, bi, off);
                if (ob < bd || (ob == bd && oi < bi)) { bd = ob; bi = oi; }
            }
            ix = bi;
        }

        int r = row0 + rloc;
        const float* q = cbq + (size_t)ix * LAT;
        float4 qv = *(const float4*)&q[lane*4];
        float4 rv = *(const float4*)&rsm[rloc*132 + lane*4];
        double r2 = (double)rv.x*rv.x + (double)rv.y*rv.y + (double)rv.z*rv.z + (double)rv.w*rv.w;
        double q2 = (double)qv.x*qv.x + (double)qv.y*qv.y + (double)qv.z*qv.z + (double)qv.w*qv.w;
        double rq = (double)rv.x*qv.x + (double)rv.y*qv.y + (double)rv.z*qv.z + (double)rv.w*qv.w;
        double dxd = (double)qv.x - rv.x, dyd = (double)qv.y - rv.y;
        double dzd = (double)qv.z - rv.z, dwd = (double)qv.w - rv.w;
        double dq = dxd*dxd + dyd*dyd + dzd*dzd + dwd*dwd;
        #pragma unroll
        for (int off = 16; off > 0; off >>= 1) {
            r2 += __shfl_xor_sync(0xffffffffu, r2, off);
            q2 += __shfl_xor_sync(0xffffffffu, q2, off);
            rq += __shfl_xor_sync(0xffffffffu, rq, off);
            dq += __shfl_xor_sync(0xffffffffu, dq, off);
        }
        double ns = sqrt(r2), nt = sqrt(q2);
        double ins = 1.0 / (ns + 1e-12), intq = 1.0 / (nt + 1e-12);
        double ru = r2 * ins;                                        // r . u
        double ss2 = r2*ins*ins + 2.0*rq*ins*intq + q2*intq*intq;    // ||u+qh||^2
        double wn = sqrt(ss2);
        double iw = 1.0 / (wn + 1e-12);
        double rs = ru + rq * intq;                                  // r . (u+qh)
        double rw = rs * iw;                                         // r . w
        double scale = nt * ins;
        float4 qrf;
        {
            double sx = (double)rv.x*ins + (double)qv.x*intq;
            double sy = (double)rv.y*ins + (double)qv.y*intq;
            double sz = (double)rv.z*ins + (double)qv.z*intq;
            double sw = (double)rv.w*ins + (double)qv.w*intq;
            qrf.x = (float)(((double)rv.x - 2.0*rw*(sx*iw) + 2.0*ru*((double)qv.x*intq)) * scale);
            qrf.y = (float)(((double)rv.y - 2.0*rw*(sy*iw) + 2.0*ru*((double)qv.y*intq)) * scale);
            qrf.z = (float)(((double)rv.z - 2.0*rw*(sz*iw) + 2.0*ru*((double)qv.z*intq)) * scale);
            qrf.w = (float)(((double)rv.w - 2.0*rw*(sw*iw) + 2.0*ru*((double)qv.w*intq)) * scale);
        }
        size_t base = (size_t)r * LAT + lane*4;
        if (qi == 0) {
            *(float4*)&g_qout[base] = qrf;
        } else {
            float4 old = *(const float4*)&g_qout[base];
            old.x += qrf.x; old.y += qrf.y; old.z += qrf.z; old.w += qrf.w;
            *(float4*)&g_qout[base] = old;
        }
        if (qi < 3) {
            float4 nr = make_float4(rv.x - qrf.x, rv.y - qrf.y, rv.z - qrf.z, rv.w - qrf.w);
            *(float4*)&g_res[base] = nr;
        }
        if (lane == 0) {
            g_codes[r*NQ + qi] = ix;
            dq_local += dq;
        }
    }
    if (lane == 0) atomicAdd(&g_acc[qi], dq_local);
}

// ---------------- smooth loss ----------------
__global__ void k_smooth() {
    int idx = blockIdx.x * 256 + threadIdx.x;
    int cnt = 0;
    if (idx < BB * (TT - 1)) {
        int b = idx / (TT - 1), t = idx % (TT - 1);
        int a = g_codes[(b*TT + t)*NQ + 0];
        int c = g_codes[(b*TT + t + 1)*NQ + 0];
        cnt = (a != c) ? 1 : 0;
    }
    __shared__ int red[256];
    red[threadIdx.x] = cnt;
    __syncthreads();
    for (int s = 128; s > 0; s >>= 1) {
        if (threadIdx.x < s) red[threadIdx.x] += red[threadIdx.x + s];
        __syncthreads();
    }
    if (threadIdx.x == 0 && red[0]) atomicAdd(&g_acc[4], (double)red[0]);
}

// ---------------- fused decoder, channel-fastest smem layouts + FFMA2 ----------------
// insm[(c*5+l)*8 + ch], hsm[(o*5+l)*8 + ch]: chunk-pairs load pre-packed (broadcast LDS).
__global__ __launch_bounds__(256) void k_dec(const float* __restrict__ b1,
                                             const float* __restrict__ b2) {
    extern __shared__ float sm[];
    float* insm = sm;                  // 660 * 8
    float* hsm  = sm + 660*8;          // 2560 * 8
    float* red  = hsm + 2560*8;        // 256
    int tid = threadIdx.x;
    int g0 = blockIdx.x * 8;

    for (int e = tid; e < 8*660; e += 256) {
        int ch = e / 660, rem = e % 660;
        int c = rem / 5, l = rem % 5;
        int g = g0 + ch;
        int b = g / COUNT_DEC, n = g % COUNT_DEC;
        int t = n*5 + l;
        float v;
        if (c < 128) v = g_qout[((size_t)b*TT + t)*LAT + c];
        else         v = (float)g_codes[(b*TT + t)*NQ + (c - 128)];
        insm[(c*5 + l)*8 + ch] = v;
    }
    __syncthreads();

    // phase 1: dec1 conv K=5 pad 2 over L=5, relu; acc packed over chunk-pairs
    for (int op = 0; op < 2; op++) {
        int o = tid + op*256;
        float bbv = b1[o];
        ull accp[4][5];                // [ch-pair][l]
        #pragma unroll
        for (int cp = 0; cp < 4; cp++)
            #pragma unroll
            for (int l = 0; l < 5; l++) accp[cp][l] = pack2(bbv, bbv);
        for (int c = 0; c < 132; c++) {
            ull inp[5][4];             // [l][ch-pair], broadcast loads
            #pragma unroll
            for (int l = 0; l < 5; l++) {
                ulonglong2 a  = *(const ulonglong2*)&insm[(c*5 + l)*8];
                ulonglong2 bq = *(const ulonglong2*)&insm[(c*5 + l)*8 + 4];
                inp[l][0] = a.x; inp[l][1] = a.y; inp[l][2] = bq.x; inp[l][3] = bq.y;
            }
            #pragma unroll
            for (int j = 0; j < 5; j++) {
                float wv = g_w1t[(c*5 + j)*512 + o];
                ull wp = pack2(wv, wv);
                #pragma unroll
                for (int l = 0; l < 5; l++) {
                    int p = l + j - 2;
                    if (p >= 0 && p < 5) {
                        #pragma unroll
                        for (int cp = 0; cp < 4; cp++)
                            accp[cp][l] = fma2(wp, inp[p][cp], accp[cp][l]);
                    }
                }
            }
        }
        #pragma unroll
        for (int l = 0; l < 5; l++) {
            ull r0, r1, r2, r3;
            {
                float2 h0 = unpack2(accp[0][l]); r0 = pack2(fmaxf(h0.x, 0.f), fmaxf(h0.y, 0.f));
                float2 h1 = unpack2(accp[1][l]); r1 = pack2(fmaxf(h1.x, 0.f), fmaxf(h1.y, 0.f));
                float2 h2 = unpack2(accp[2][l]); r2 = pack2(fmaxf(h2.x, 0.f), fmaxf(h2.y, 0.f));
                float2 h3 = unpack2(accp[3][l]); r3 = pack2(fmaxf(h3.x, 0.f), fmaxf(h3.y, 0.f));
            }
            ulonglong2 s0; s0.x = r0; s0.y = r1;
            ulonglong2 s1; s1.x = r2; s1.y = r3;
            *(ulonglong2*)&hsm[(o*5 + l)*8]     = s0;
            *(ulonglong2*)&hsm[(o*5 + l)*8 + 4] = s1;
        }
    }
    __syncthreads();

    // phase 2: dec2 conv K=3 pad 1, packed over chunk-pairs, subtract true, square
    int o2 = tid & 127, gp = tid >> 7;
    float bb2 = b2[o2];
    ull accp2[2][5];                   // [cc-pair][l]
    #pragma unroll
    for (int cp = 0; cp < 2; cp++)
        #pragma unroll
        for (int l = 0; l < 5; l++) accp2[cp][l] = pack2(bb2, bb2);
    for (int c = 0; c < 512; c++) {
        ulonglong2 hrp[5];             // [p] -> two cc-pairs (broadcast per gp)
        #pragma unroll
        for (int p = 0; p < 5; p++)
            hrp[p] = *(const ulonglong2*)&hsm[(c*5 + p)*8 + gp*4];
        #pragma unroll
        for (int j = 0; j < 3; j++) {
            float wv = g_w2t[(c*3 + j)*128 + o2];
            ull wp = pack2(wv, wv);
            #pragma unroll
            for (int l = 0; l < 5; l++) {
                int p = l + j - 1;
                if (p >= 0 && p < 5) {
                    accp2[0][l] = fma2(wp, hrp[p].x, accp2[0][l]);
                    accp2[1][l] = fma2(wp, hrp[p].y, accp2[1][l]);
                }
            }
        }
    }
    float lsum = 0.f;
    #pragma unroll
    for (int cp = 0; cp < 2; cp++) {
        #pragma unroll
        for (int half = 0; half < 2; half++) {
            int cc = cp*2 + half;
            int g = g0 + gp*4 + cc;
            int b = g / COUNT_DEC, n = g % COUNT_DEC;
            #pragma unroll
            for (int l = 0; l < 5; l++) {
                float2 h = unpack2(accp2[cp][l]);
                float v = half == 0 ? h.x : h.y;
                int t = (n + 1)*5 + l;
                float d = v - g_qout[((size_t)b*TT + t)*LAT + o2];
                lsum += d*d;
            }
        }
    }
    red[tid] = lsum;
    __syncthreads();
    for (int s = 128; s > 0; s >>= 1) {
        if (tid < s) red[tid] += red[tid + s];
        __syncthreads();
    }
    if (tid == 0) atomicAdd(&g_acc[5], (double)red[0]);
}

// ---------------- outputs ----------------
__global__ void k_codes_out(float* __restrict__ out, int out_size) {
    int i = blockIdx.x * 256 + threadIdx.x;
    if (i < BB*TT*NQ && i < out_size) out[i] = (float)g_codes[i];
}

__global__ void k_final(float* __restrict__ out, int out_size) {
    if (threadIdx.x != 0 || blockIdx.x != 0) return;
    double nv = (double)BB * TT * LAT;                  // 16,384,000
    double vq = (g_acc[0]/nv + g_acc[1]/nv + g_acc[2]/nv + g_acc[3]/nv) / 4.0;
    double recon = g_acc[5] / ((double)NCHUNKS * LAT * 5);
    double smooth = g_acc[4] / ((double)BB * (TT - 1));
    double loss = recon * 1.0 + vq * 1.0 + smooth * 0.1;
    int base = BB*TT*NQ;
    if (base + 0 < out_size) out[base + 0] = (float)loss;
    if (base + 1 < out_size) out[base + 1] = (float)recon;
    if (base + 2 < out_size) out[base + 2] = (float)vq;
    if (base + 3 < out_size) out[base + 3] = (float)smooth;
}

// ---------------- launch ----------------
extern "C" void kernel_launch(void* const* d_in, const int* in_sizes, int n_in,
                              void* d_out, int out_size) {
    const float* traj = (const float*)d_in[0];
    // d_in[1] = masks (unused by reference forward)
    const float* e1w  = (const float*)d_in[2];
    const float* e1b  = (const float*)d_in[3];
    const float* e2aw = (const float*)d_in[4];
    const float* e2ab = (const float*)d_in[5];
    const float* e2bw = (const float*)d_in[6];
    const float* e2bb = (const float*)d_in[7];
    const float* d1w  = (const float*)d_in[8];
    const float* d1b  = (const float*)d_in[9];
    const float* d2w  = (const float*)d_in[10];
    const float* d2b  = (const float*)d_in[11];
    const float* cb   = (const float*)d_in[12];
    float* out = (float*)d_out;

    const int VQ_SMEM  = (64*132 + 128*132 + 128) * 4;      // 101,888 B
    const int DEC_SMEM = (660*8 + 2560*8 + 256) * 4;        // 104,064 B
    cudaFuncSetAttribute(k_vq,  cudaFuncAttributeMaxDynamicSharedMemorySize, VQ_SMEM);
    cudaFuncSetAttribute(k_dec, cudaFuncAttributeMaxDynamicSharedMemorySize, DEC_SMEM);

    void *p_z3 = nullptr, *p_ze = nullptr;
    cudaGetSymbolAddress(&p_z3, g_z3);
    cudaGetSymbolAddress(&p_ze, g_ze);

    k_zero_acc<<<1, 32>>>();
    k_tw1<<<(512*660 + 255)/256, 256>>>(d1w);
    k_tw2<<<(128*1536 + 255)/256, 256>>>(d2w);
    k_cbnorm<<<(NQ*KCB)/256, 256>>>(cb);
    k_enc1<<<dim3(TN/16, BB), 256>>>(traj, e1w, e1b);
    // enc2a: 512->512, K=5, relu, interp-fused input
    k_conv2<5, true, false, true><<<dim3(TT/64, HID/128, BB), 256>>>(nullptr, e2aw, e2ab, (float*)p_z3);
    // enc2b: 512->128, K=7, transposed out (B,T,128)
    k_conv2<7, false, true, false><<<dim3(TT/64, LAT/128, BB), 256>>>((const float*)p_z3, e2bw, e2bb, (float*)p_ze);
    for (int qi = 0; qi < NQ; qi++) {
        k_vq<<<(BB*TT)/64, 256, VQ_SMEM>>>(cb, qi);
    }
    k_smooth<<<(BB*(TT-1) + 255)/256, 256>>>();
    k_dec<<<NCHUNKS/8, 256, DEC_SMEM>>>(d1b, d2b);
    k_codes_out<<<(BB*TT*NQ)/256, 256>>>(out, out_size);
    k_final<<<1, 32>>>(out, out_size);
}

// round 7
// speedup vs baseline: 1.0815x; 1.0815x over previous
#include <cuda_runtime.h>
#include <math.h>

#define BB   16
#define TT   8000
#define TN   800
#define HID  512
#define LAT  128
#define KCB  1024
#define NQ   4
#define COUNT_DEC 1599
#define NCHUNKS   25584   // BB * COUNT_DEC
#define RESCORE_TAU 4e-3f

// ---------------- scratch (device globals; no allocation allowed) ----------------
__device__ float g_z1[BB*HID*TN];        // enc1 out (B,512,800)
__device__ float g_z3[(size_t)BB*HID*TT];// enc2a out (B,512,8000)
__device__ float g_ze[(size_t)BB*TT*LAT];// enc2b out, transposed (B,T,128)
__device__ float g_res[(size_t)BB*TT*LAT];
__device__ float g_qout[(size_t)BB*TT*LAT];
__device__ int   g_codes[BB*TT*NQ];
__device__ float g_cbn[NQ*KCB];
__device__ float g_w1t[132*5*512];       // dec1 weights transposed: [(c*5+j)*512 + o]
__device__ float g_w2t[512*3*128];       // dec2 weights transposed: [(c*3+j)*128 + o]
__device__ double g_acc[8];  // [0..3] vq sums, [4] smooth count, [5] recon sum

// ---------------- tiny utility kernels ----------------
__global__ void k_zero_acc() {
    if (threadIdx.x < 8) g_acc[threadIdx.x] = 0.0;
}

__global__ void k_tw1(const float* __restrict__ w1) {
    int idx = blockIdx.x * 256 + threadIdx.x;
    if (idx >= 512*660) return;
    int o = idx / 660, r = idx % 660;
    g_w1t[r*512 + o] = w1[idx];     // r = c*5 + j already
}
__global__ void k_tw2(const float* __restrict__ w2) {
    int idx = blockIdx.x * 256 + threadIdx.x;
    if (idx >= 128*1536) return;
    int o = idx / 1536, r = idx % 1536;
    g_w2t[r*128 + o] = w2[idx];     // r = c*3 + j already
}

// ---------------- enc1: (B,20,800) -> relu conv K=3 -> (B,512,800) ----------------
__global__ __launch_bounds__(256) void k_enc1(const float* __restrict__ traj,
                                              const float* __restrict__ w,
                                              const float* __restrict__ bias) {
    __shared__ float xs[20][18];
    int b = blockIdx.y, t0 = blockIdx.x * 16;
    int tid = threadIdx.x;
    for (int e = tid; e < 20*18; e += 256) {
        int i = e / 18, u = e % 18;
        int tg = t0 + u - 1;
        float v = 0.f;
        if (tg >= 0 && tg < TN) v = traj[((size_t)b*2 + (i/10))*TT + tg*10 + (i%10)];
        xs[i][u] = v;
    }
    __syncthreads();
    int o0 = tid, o1 = tid + 256;
    float acc0[16], acc1[16];
    float b0 = bias[o0], b1v = bias[o1];
    #pragma unroll
    for (int t = 0; t < 16; t++) { acc0[t] = 0.f; acc1[t] = 0.f; }
    for (int i = 0; i < 20; i++) {
        #pragma unroll
        for (int j = 0; j < 3; j++) {
            float w0 = w[(o0*20 + i)*3 + j];
            float w1 = w[(o1*20 + i)*3 + j];
            #pragma unroll
            for (int t = 0; t < 16; t++) {
                float x = xs[i][t + j];
                acc0[t] += w0 * x;
                acc1[t] += w1 * x;
            }
        }
    }
    #pragma unroll
    for (int t = 0; t < 16; t++) {
        g_z1[((size_t)b*HID + o0)*TN + t0 + t] = fmaxf(acc0[t] + b0, 0.f);
        g_z1[((size_t)b*HID + o1)*TN + t0 + t] = fmaxf(acc1[t] + b1v, 0.f);
    }
}

// ---------------- conv v2: 64T x 128OC tile, thread = 4T x 8OC ----------------
// INTERP: compute pooled+interp value from g_z1 on the fly (enc2a input).
template<int K, bool RELU, bool TROUT, bool INTERP>
__global__ __launch_bounds__(256) void k_conv2(const float* __restrict__ in,
                                               const float* __restrict__ wt,
                                               const float* __restrict__ bias,
                                               float* __restrict__ out) {
    constexpr int P   = (K - 1) / 2;
    constexpr int ZW  = 64 + K - 1;                    // 68 (K=5) / 70 (K=7)
    constexpr int ZWP = (ZW % 4 == 0) ? ZW : ZW + (4 - ZW % 4);  // 68 / 72
    constexpr int NZ4 = (K + 6) / 4;                   // 2 / 3
    constexpr int PW  = 132;                           // wsm pitch (4-way wr conflict, aligned reads)
    __shared__ float wsm[8 * K * PW];
    __shared__ float zsm[8 * ZWP];
    int tid = threadIdx.x;
    int tx = tid & 15, ty = tid >> 4;
    int t0 = blockIdx.x * 64, ob = blockIdx.y * 128, b = blockIdx.z;
    int OCt = gridDim.y * 128;
    int o = ob + ty * 8, tt = tx * 4;

    float acc[8][4], sum[8][4];
    #pragma unroll
    for (int c = 0; c < 8; c++)
        #pragma unroll
        for (int tl = 0; tl < 4; tl++) { acc[c][tl] = 0.f; sum[c][tl] = 0.f; }

    for (int chunk = 0; chunk < 64; chunk++) {
        int ic0 = chunk * 8;
        __syncthreads();
        // weights: contiguous global reads, strided smem writes (pitch 132)
        for (int e = tid; e < 8 * K * 128; e += 256) {
            int ol = e / (8 * K);
            int r  = e - ol * (8 * K);
            int i  = r / K, j = r - i * K;
            wsm[(i*K + j)*PW + ol] = wt[((size_t)(ob + ol)*512 + ic0 + i)*K + j];
        }
        // input tile
        for (int e = tid; e < 8 * ZW; e += 256) {
            int i = e / ZW, u = e - i * ZW;
            int tg = t0 + u - P;
            float v = 0.f;
            if (tg >= 0 && tg < TT) {
                if (INTERP) {
                    const float* row = g_z1 + ((size_t)b*HID + ic0 + i)*TN;
                    float src = fmaxf(((float)tg + 0.5f)*0.5f - 0.5f, 0.0f);
                    int i0 = (int)src;
                    int i1 = min(i0 + 1, 3999);
                    float frac = src - (float)i0;
                    float v0 = row[i0 / 5];
                    float v1 = row[i1 / 5];
                    v = v0 * (1.0f - frac) + v1 * frac;
                } else {
                    v = in[((size_t)b*HID + ic0 + i)*TT + tg];
                }
            }
            zsm[i*ZWP + u] = v;
        }
        __syncthreads();
        #pragma unroll
        for (int i = 0; i < 8; i++) {
            float zr[NZ4 * 4];
            #pragma unroll
            for (int q = 0; q < NZ4; q++)
                *(float4*)&zr[q*4] = *(const float4*)&zsm[i*ZWP + tt + q*4];
            #pragma unroll
            for (int j = 0; j < K; j++) {
                float4 wa = *(const float4*)&wsm[(i*K + j)*PW + ty*8];
                float4 wb = *(const float4*)&wsm[(i*K + j)*PW + ty*8 + 4];
                #pragma unroll
                for (int tl = 0; tl < 4; tl++) {
                    float z = zr[tl + j];
                    acc[0][tl] += wa.x * z;
                    acc[1][tl] += wa.y * z;
                    acc[2][tl] += wa.z * z;
                    acc[3][tl] += wa.w * z;
                    acc[4][tl] += wb.x * z;
                    acc[5][tl] += wb.y * z;
                    acc[6][tl] += wb.z * z;
                    acc[7][tl] += wb.w * z;
                }
            }
        }
        if ((chunk & 3) == 3) {   // flush short fp32 chains
            #pragma unroll
            for (int c = 0; c < 8; c++)
                #pragma unroll
                for (int tl = 0; tl < 4; tl++) { sum[c][tl] += acc[c][tl]; acc[c][tl] = 0.f; }
        }
    }

    float resv[8][4];
    #pragma unroll
    for (int c = 0; c < 8; c++) {
        float bv = bias[o + c];
        #pragma unroll
        for (int tl = 0; tl < 4; tl++) {
            float v = sum[c][tl] + bv;
            if (RELU) v = fmaxf(v, 0.f);
            resv[c][tl] = v;
        }
    }
    if (!TROUT) {
        #pragma unroll
        for (int c = 0; c < 8; c++) {
            float4 v = make_float4(resv[c][0], resv[c][1], resv[c][2], resv[c][3]);
            *(float4*)&out[((size_t)b*OCt + o + c)*TT + t0 + tt] = v;
        }
    } else {
        #pragma unroll
        for (int tl = 0; tl < 4; tl++) {
            float4 va = make_float4(resv[0][tl], resv[1][tl], resv[2][tl], resv[3][tl]);
            float4 vb = make_float4(resv[4][tl], resv[5][tl], resv[6][tl], resv[7][tl]);
            *(float4*)&out[((size_t)b*TT + t0 + tt + tl)*OCt + o]     = va;
            *(float4*)&out[((size_t)b*TT + t0 + tt + tl)*OCt + o + 4] = vb;
        }
    }
}

// ---------------- codebook squared norms (double, stored fp32) ----------------
__global__ void k_cbnorm(const float* __restrict__ cb) {
    int id = blockIdx.x * 256 + threadIdx.x;
    if (id >= NQ * KCB) return;
    const float* r = cb + (size_t)id * LAT;
    double s = 0.0;
    for (int d = 0; d < LAT; d++) {
        double v = (double)r[d];
        s += v * v;
    }
    g_cbn[id] = (float)s;
}

// ---------------- residual VQ, one codebook per launch ----------------
__global__ __launch_bounds__(256) void k_vq(const float* __restrict__ cb_all, int qi) {
    extern __shared__ float sm[];
    float* rsm = sm;                      // 64 x 132
    float* csm = sm + 64*132;             // 128 x 132
    float* nsm = csm + 128*132;           // 128
    int tid = threadIdx.x, lane = tid & 31, w = tid >> 5;
    int row0 = blockIdx.x * 64;
    const float* src = (qi == 0) ? g_ze : g_res;
    for (int e = tid; e < 64*32; e += 256) {
        int lr = e >> 5, d4 = (e & 31) * 4;
        float4 v = *(const float4*)&src[(size_t)(row0 + lr)*LAT + d4];
        *(float4*)&rsm[lr*132 + d4] = v;
    }
    const float* cbq = cb_all + (size_t)qi * KCB * LAT;
    float bestv[8], secv[8]; int besti[8];
    #pragma unroll
    for (int rr = 0; rr < 8; rr++) { bestv[rr] = 3.4e38f; secv[rr] = 3.4e38f; besti[rr] = 0; }

    for (int cc = 0; cc < 8; cc++) {
        __syncthreads();
        for (int e = tid; e < 128*32; e += 256) {
            int k = e >> 5, d4 = (e & 31) * 4;
            float4 v = *(const float4*)&cbq[(size_t)(cc*128 + k)*LAT + d4];
            *(float4*)&csm[k*132 + d4] = v;
        }
        if (tid < 128) nsm[tid] = g_cbn[qi*KCB + cc*128 + tid];
        __syncthreads();
        float acc[8][4];
        #pragma unroll
        for (int rr = 0; rr < 8; rr++)
            #pragma unroll
            for (int c = 0; c < 4; c++) acc[rr][c] = 0.f;
        #pragma unroll 2
        for (int d = 0; d < 128; d += 4) {
            float4 cv[4];
            #pragma unroll
            for (int c = 0; c < 4; c++) cv[c] = *(const float4*)&csm[(lane*4 + c)*132 + d];
            #pragma unroll
            for (int rr = 0; rr < 8; rr++) {
                float4 rv = *(const float4*)&rsm[(w*8 + rr)*132 + d];
                #pragma unroll
                for (int c = 0; c < 4; c++) {
                    acc[rr][c] += rv.x*cv[c].x + rv.y*cv[c].y + rv.z*cv[c].z + rv.w*cv[c].w;
                }
            }
        }
        #pragma unroll
        for (int rr = 0; rr < 8; rr++) {
            #pragma unroll
            for (int c = 0; c < 4; c++) {
                float dist = nsm[lane*4 + c] - 2.0f * acc[rr][c];
                int idx = cc*128 + lane*4 + c;
                if (dist < bestv[rr]) { secv[rr] = bestv[rr]; bestv[rr] = dist; besti[rr] = idx; }
                else if (dist < secv[rr]) { secv[rr] = dist; }
            }
        }
    }

    double dq_local = 0.0;
    for (int rr = 0; rr < 8; rr++) {
        float v1 = bestv[rr]; int i1 = besti[rr]; float v2 = secv[rr];
        #pragma unroll
        for (int off = 16; off > 0; off >>= 1) {
            float ov1 = __shfl_xor_sync(0xffffffffu, v1, off);
            int   oi1 = __shfl_xor_sync(0xffffffffu, i1, off);
            float ov2 = __shfl_xor_sync(0xffffffffu, v2, off);
            if (ov1 < v1 || (ov1 == v1 && oi1 < i1)) {
                v2 = fminf(v1, ov2);
                v1 = ov1; i1 = oi1;
            } else {
                v2 = fminf(v2, ov1);
            }
        }
        int ix = i1;
        int rloc = w*8 + rr;
        // ---- exact fp64 rescore when the fp32 margin is too small ----
        if (v2 - v1 < RESCORE_TAU) {
            double bd = 1e300; int bi = 0x7fffffff;
            for (int kk = 0; kk < 32; kk++) {
                int k = kk*32 + lane;
                const float* cr = cbq + (size_t)k * LAT;
                double s = 0.0;
                for (int d = 0; d < 128; d++) {
                    double cd = (double)cr[d];
                    double rd = (double)rsm[rloc*132 + d];
                    s += cd*cd - 2.0*rd*cd;
                }
                if (s < bd || (s == bd && k < bi)) { bd = s; bi = k; }
            }
            #pragma unroll
            for (int off = 16; off > 0; off >>= 1) {
                double ob = __shfl_xor_sync(0xffffffffu, bd, off);
                int    oi = __shfl_xor_sync(0xffffffffu, bi, off);
                if (ob < bd || (ob == bd && oi < bi)) { bd = ob; bi = oi; }
            }
            ix = bi;
        }

        int r = row0 + rloc;
        const float* q = cbq + (size_t)ix * LAT;
        float4 qv = *(const float4*)&q[lane*4];
        float4 rv = *(const float4*)&rsm[rloc*132 + lane*4];
        double r2 = (double)rv.x*rv.x + (double)rv.y*rv.y + (double)rv.z*rv.z + (double)rv.w*rv.w;
        double q2 = (double)qv.x*qv.x + (double)qv.y*qv.y + (double)qv.z*qv.z + (double)qv.w*qv.w;
        double rq = (double)rv.x*qv.x + (double)rv.y*qv.y + (double)rv.z*qv.z + (double)rv.w*qv.w;
        double dxd = (double)qv.x - rv.x, dyd = (double)qv.y - rv.y;
        double dzd = (double)qv.z - rv.z, dwd = (double)qv.w - rv.w;
        double dq = dxd*dxd + dyd*dyd + dzd*dzd + dwd*dwd;
        #pragma unroll
        for (int off = 16; off > 0; off >>= 1) {
            r2 += __shfl_xor_sync(0xffffffffu, r2, off);
            q2 += __shfl_xor_sync(0xffffffffu, q2, off);
            rq += __shfl_xor_sync(0xffffffffu, rq, off);
            dq += __shfl_xor_sync(0xffffffffu, dq, off);
        }
        double ns = sqrt(r2), nt = sqrt(q2);
        double ins = 1.0 / (ns + 1e-12), intq = 1.0 / (nt + 1e-12);
        double ru = r2 * ins;                                        // r . u
        double ss2 = r2*ins*ins + 2.0*rq*ins*intq + q2*intq*intq;    // ||u+qh||^2
        double wn = sqrt(ss2);
        double iw = 1.0 / (wn + 1e-12);
        double rs = ru + rq * intq;                                  // r . (u+qh)
        double rw = rs * iw;                                         // r . w
        double scale = nt * ins;
        float4 qrf;
        {
            double sx = (double)rv.x*ins + (double)qv.x*intq;
            double sy = (double)rv.y*ins + (double)qv.y*intq;
            double sz = (double)rv.z*ins + (double)qv.z*intq;
            double sw = (double)rv.w*ins + (double)qv.w*intq;
            qrf.x = (float)(((double)rv.x - 2.0*rw*(sx*iw) + 2.0*ru*((double)qv.x*intq)) * scale);
            qrf.y = (float)(((double)rv.y - 2.0*rw*(sy*iw) + 2.0*ru*((double)qv.y*intq)) * scale);
            qrf.z = (float)(((double)rv.z - 2.0*rw*(sz*iw) + 2.0*ru*((double)qv.z*intq)) * scale);
            qrf.w = (float)(((double)rv.w - 2.0*rw*(sw*iw) + 2.0*ru*((double)qv.w*intq)) * scale);
        }
        size_t base = (size_t)r * LAT + lane*4;
        if (qi == 0) {
            *(float4*)&g_qout[base] = qrf;
        } else {
            float4 old = *(const float4*)&g_qout[base];
            old.x += qrf.x; old.y += qrf.y; old.z += qrf.z; old.w += qrf.w;
            *(float4*)&g_qout[base] = old;
        }
        if (qi < 3) {
            float4 nr = make_float4(rv.x - qrf.x, rv.y - qrf.y, rv.z - qrf.z, rv.w - qrf.w);
            *(float4*)&g_res[base] = nr;
        }
        if (lane == 0) {
            g_codes[r*NQ + qi] = ix;
            dq_local += dq;
        }
    }
    if (lane == 0) atomicAdd(&g_acc[qi], dq_local);
}

// ---------------- smooth loss ----------------
__global__ void k_smooth() {
    int idx = blockIdx.x * 256 + threadIdx.x;
    int cnt = 0;
    if (idx < BB * (TT - 1)) {
        int b = idx / (TT - 1), t = idx % (TT - 1);
        int a = g_codes[(b*TT + t)*NQ + 0];
        int c = g_codes[(b*TT + t + 1)*NQ + 0];
        cnt = (a != c) ? 1 : 0;
    }
    __shared__ int red[256];
    red[threadIdx.x] = cnt;
    __syncthreads();
    for (int s = 128; s > 0; s >>= 1) {
        if (threadIdx.x < s) red[threadIdx.x] += red[threadIdx.x + s];
        __syncthreads();
    }
    if (threadIdx.x == 0 && red[0]) atomicAdd(&g_acc[4], (double)red[0]);
}

// ---------------- fused decoder (dec1 + relu + dec2 + recon loss), 8 chunks/block ----------------
__global__ __launch_bounds__(256) void k_dec(const float* __restrict__ b1,
                                             const float* __restrict__ b2) {
    extern __shared__ float sm[];
    float* insm = sm;                  // 8 * 660
    float* hsm  = sm + 8*660;          // 8 * 2560
    float* red  = hsm + 8*2560;        // 256
    int tid = threadIdx.x;
    int g0 = blockIdx.x * 8;

    for (int e = tid; e < 8*660; e += 256) {
        int ch = e / 660, rem = e % 660;
        int c = rem / 5, l = rem % 5;
        int g = g0 + ch;
        int b = g / COUNT_DEC, n = g % COUNT_DEC;
        int t = n*5 + l;
        float v;
        if (c < 128) v = g_qout[((size_t)b*TT + t)*LAT + c];
        else         v = (float)g_codes[(b*TT + t)*NQ + (c - 128)];
        insm[ch*660 + c*5 + l] = v;
    }
    __syncthreads();

    // phase 1: dec1 conv K=5 pad 2 over L=5, relu
    for (int op = 0; op < 2; op++) {
        int o = tid + op*256;
        float acc[8][5];
        float bbv = b1[o];
        #pragma unroll
        for (int ch = 0; ch < 8; ch++)
            #pragma unroll
            for (int l = 0; l < 5; l++) acc[ch][l] = bbv;
        for (int c = 0; c < 132; c++) {
            float inr[8][5];
            #pragma unroll
            for (int ch = 0; ch < 8; ch++)
                #pragma unroll
                for (int l = 0; l < 5; l++) inr[ch][l] = insm[ch*660 + c*5 + l];
            #pragma unroll
            for (int j = 0; j < 5; j++) {
                float wv = g_w1t[(c*5 + j)*512 + o];
                #pragma unroll
                for (int l = 0; l < 5; l++) {
                    int p = l + j - 2;
                    if (p >= 0 && p < 5) {
                        #pragma unroll
                        for (int ch = 0; ch < 8; ch++) acc[ch][l] += wv * inr[ch][p];
                    }
                }
            }
        }
        #pragma unroll
        for (int ch = 0; ch < 8; ch++)
            #pragma unroll
            for (int l = 0; l < 5; l++)
                hsm[ch*2560 + o*5 + l] = fmaxf(acc[ch][l], 0.f);
    }
    __syncthreads();

    // phase 2: dec2 conv K=3 pad 1, subtract true chunk, square
    int o2 = tid & 127, gp = tid >> 7;
    float acc2[4][5];
    float bb2 = b2[o2];
    #pragma unroll
    for (int cc = 0; cc < 4; cc++)
        #pragma unroll
        for (int l = 0; l < 5; l++) acc2[cc][l] = bb2;
    for (int c = 0; c < 512; c++) {
        float hr[4][5];
        #pragma unroll
        for (int cc = 0; cc < 4; cc++)
            #pragma unroll
            for (int l = 0; l < 5; l++) hr[cc][l] = hsm[(gp*4 + cc)*2560 + c*5 + l];
        #pragma unroll
        for (int j = 0; j < 3; j++) {
            float wv = g_w2t[(c*3 + j)*128 + o2];
            #pragma unroll
            for (int l = 0; l < 5; l++) {
                int p = l + j - 1;
                if (p >= 0 && p < 5) {
                    #pragma unroll
                    for (int cc = 0; cc < 4; cc++) acc2[cc][l] += wv * hr[cc][p];
                }
            }
        }
    }
    float lsum = 0.f;
    #pragma unroll
    for (int cc = 0; cc < 4; cc++) {
        int g = g0 + gp*4 + cc;
        int b = g / COUNT_DEC, n = g % COUNT_DEC;
        #pragma unroll
        for (int l = 0; l < 5; l++) {
            int t = (n + 1)*5 + l;
            float d = acc2[cc][l] - g_qout[((size_t)b*TT + t)*LAT + o2];
            lsum += d*d;
        }
    }
    red[tid] = lsum;
    __syncthreads();
    for (int s = 128; s > 0; s >>= 1) {
        if (tid < s) red[tid] += red[tid + s];
        __syncthreads();
    }
    if (tid == 0) atomicAdd(&g_acc[5], (double)red[0]);
}

// ---------------- outputs ----------------
__global__ void k_codes_out(float* __restrict__ out, int out_size) {
    int i = blockIdx.x * 256 + threadIdx.x;
    if (i < BB*TT*NQ && i < out_size) out[i] = (float)g_codes[i];
}

__global__ void k_final(float* __restrict__ out, int out_size) {
    if (threadIdx.x != 0 || blockIdx.x != 0) return;
    double nv = (double)BB * TT * LAT;                  // 16,384,000
    double vq = (g_acc[0]/nv + g_acc[1]/nv + g_acc[2]/nv + g_acc[3]/nv) / 4.0;
    double recon = g_acc[5] / ((double)NCHUNKS * LAT * 5);
    double smooth = g_acc[4] / ((double)BB * (TT - 1));
    double loss = recon * 1.0 + vq * 1.0 + smooth * 0.1;
    int base = BB*TT*NQ;
    if (base + 0 < out_size) out[base + 0] = (float)loss;
    if (base + 1 < out_size) out[base + 1] = (float)recon;
    if (base + 2 < out_size) out[base + 2] = (float)vq;
    if (base + 3 < out_size) out[base + 3] = (float)smooth;
}

// ---------------- launch ----------------
// NOTE: launch order arranged so index 3 (the one ncu profiles) = k_conv2<5> (enc2a).
extern "C" void kernel_launch(void* const* d_in, const int* in_sizes, int n_in,
                              void* d_out, int out_size) {
    const float* traj = (const float*)d_in[0];
    // d_in[1] = masks (unused by reference forward)
    const float* e1w  = (const float*)d_in[2];
    const float* e1b  = (const float*)d_in[3];
    const float* e2aw = (const float*)d_in[4];
    const float* e2ab = (const float*)d_in[5];
    const float* e2bw = (const float*)d_in[6];
    const float* e2bb = (const float*)d_in[7];
    const float* d1w  = (const float*)d_in[8];
    const float* d1b  = (const float*)d_in[9];
    const float* d2w  = (const float*)d_in[10];
    const float* d2b  = (const float*)d_in[11];
    const float* cb   = (const float*)d_in[12];
    float* out = (float*)d_out;

    const int VQ_SMEM  = (64*132 + 128*132 + 128) * 4;      // 101,888 B
    const int DEC_SMEM = (8*660 + 8*2560 + 256) * 4;        // 104,064 B
    cudaFuncSetAttribute(k_vq,  cudaFuncAttributeMaxDynamicSharedMemorySize, VQ_SMEM);
    cudaFuncSetAttribute(k_dec, cudaFuncAttributeMaxDynamicSharedMemorySize, DEC_SMEM);

    void *p_z3 = nullptr, *p_ze = nullptr;
    cudaGetSymbolAddress(&p_z3, g_z3);
    cudaGetSymbolAddress(&p_ze, g_ze);

    k_zero_acc<<<1, 32>>>();                                              // 0
    k_enc1<<<dim3(TN/16, BB), 256>>>(traj, e1w, e1b);                     // 1
    k_tw1<<<(512*660 + 255)/256, 256>>>(d1w);                             // 2
    // enc2a: 512->512, K=5, relu, interp-fused input                     // 3 <- ncu target
    k_conv2<5, true, false, true><<<dim3(TT/64, HID/128, BB), 256>>>(nullptr, e2aw, e2ab, (float*)p_z3);
    // enc2b: 512->128, K=7, transposed out (B,T,128)                     // 4
    k_conv2<7, false, true, false><<<dim3(TT/64, LAT/128, BB), 256>>>((const float*)p_z3, e2bw, e2bb, (float*)p_ze);
    k_tw2<<<(128*1536 + 255)/256, 256>>>(d2w);                            // 5
    k_cbnorm<<<(NQ*KCB)/256, 256>>>(cb);                                  // 6
    for (int qi = 0; qi < NQ; qi++) {
        k_vq<<<(BB*TT)/64, 256, VQ_SMEM>>>(cb, qi);                       // 7-10
    }
    k_smooth<<<(BB*(TT-1) + 255)/256, 256>>>();                           // 11
    k_dec<<<NCHUNKS/8, 256, DEC_SMEM>>>(d1b, d2b);                        // 12
    k_codes_out<<<(BB*TT*NQ)/256, 256>>>(out, out_size);                  // 13
    k_final<<<1, 32>>>(out, out_size);                                    // 14
}

// round 9
// speedup vs baseline: 1.4098x; 1.3035x over previous
#include <cuda_runtime.h>
#include <stdint.h>
#include <math.h>

#define BB   16
#define TT   8000
#define TN   800
#define HID  512
#define LAT  128
#define KCB  1024
#define NQ   4
#define COUNT_DEC 1599
#define NCHUNKS   25584   // BB * COUNT_DEC
#define RESCORE_TAU 4e-3f

// ---------------- scratch (device globals; no allocation allowed) ----------------
__device__ float g_z1[BB*HID*TN];        // enc1 out (B,512,800)
__device__ float g_z3[(size_t)BB*HID*TT];// enc2a out (B,512,8000)
__device__ float g_ze[(size_t)BB*TT*LAT];// enc2b out, transposed (B,T,128)
__device__ float g_res[(size_t)BB*TT*LAT];
__device__ float g_qout[(size_t)BB*TT*LAT];
__device__ int   g_codes[BB*TT*NQ];
__device__ float g_cbn[NQ*KCB];
__device__ float g_w1t[132*5*512];       // dec1 weights transposed: [(c*5+j)*512 + o]
__device__ float g_w2t[512*3*128];       // dec2 weights transposed: [(c*3+j)*128 + o]
__device__ float g_wa[4*64*8*5*132];     // enc2a weights pre-staged (smem image)
__device__ float g_wb[1*64*8*7*132];     // enc2b weights pre-staged
__device__ double g_acc[8];  // [0..3] vq sums, [4] smooth count, [5] recon sum

// ---------------- tiny utility kernels ----------------
__global__ void k_zero_acc() {
    if (threadIdx.x < 8) g_acc[threadIdx.x] = 0.0;
}

__global__ void k_tw1(const float* __restrict__ w1) {
    int idx = blockIdx.x * 256 + threadIdx.x;
    if (idx >= 512*660) return;
    int o = idx / 660, r = idx % 660;
    g_w1t[r*512 + o] = w1[idx];     // r = c*5 + j already
}
__global__ void k_tw2(const float* __restrict__ w2) {
    int idx = blockIdx.x * 256 + threadIdx.x;
    if (idx >= 128*1536) return;
    int o = idx / 1536, r = idx % 1536;
    g_w2t[r*128 + o] = w2[idx];     // r = c*3 + j already
}

// stage conv weights into smem image: dst[(ocb*64+chunk)*8*K*132 + (i*K+j)*132 + ol]
__global__ void k_wstage(const float* __restrict__ wt, float* __restrict__ dst,
                         int K, int OCB) {
    int idx = blockIdx.x * 256 + threadIdx.x;
    int total = OCB * 64 * 8 * K * 128;
    if (idx >= total) return;
    int ol = idx & 127;
    int r  = idx >> 7;
    int j  = r % K;  r /= K;
    int i  = r & 7;  r >>= 3;
    int chunk = r & 63;
    int ocb   = r >> 6;
    dst[((size_t)(ocb*64 + chunk))*(8*K*132) + (i*K + j)*132 + ol] =
        wt[((size_t)(ocb*128 + ol)*512 + chunk*8 + i)*K + j];
}

// ---------------- enc1: (B,20,800) -> relu conv K=3 -> (B,512,800) ----------------
__global__ __launch_bounds__(256) void k_enc1(const float* __restrict__ traj,
                                              const float* __restrict__ w,
                                              const float* __restrict__ bias) {
    __shared__ float xs[20][18];
    int b = blockIdx.y, t0 = blockIdx.x * 16;
    int tid = threadIdx.x;
    for (int e = tid; e < 20*18; e += 256) {
        int i = e / 18, u = e % 18;
        int tg = t0 + u - 1;
        float v = 0.f;
        if (tg >= 0 && tg < TN) v = traj[((size_t)b*2 + (i/10))*TT + tg*10 + (i%10)];
        xs[i][u] = v;
    }
    __syncthreads();
    int o0 = tid, o1 = tid + 256;
    float acc0[16], acc1[16];
    float b0 = bias[o0], b1v = bias[o1];
    #pragma unroll
    for (int t = 0; t < 16; t++) { acc0[t] = 0.f; acc1[t] = 0.f; }
    for (int i = 0; i < 20; i++) {
        #pragma unroll
        for (int j = 0; j < 3; j++) {
            float w0 = w[(o0*20 + i)*3 + j];
            float w1 = w[(o1*20 + i)*3 + j];
            #pragma unroll
            for (int t = 0; t < 16; t++) {
                float x = xs[i][t + j];
                acc0[t] += w0 * x;
                acc1[t] += w1 * x;
            }
        }
    }
    #pragma unroll
    for (int t = 0; t < 16; t++) {
        g_z1[((size_t)b*HID + o0)*TN + t0 + t] = fmaxf(acc0[t] + b0, 0.f);
        g_z1[((size_t)b*HID + o1)*TN + t0 + t] = fmaxf(acc1[t] + b1v, 0.f);
    }
}

// ---------------- conv v3: 128OC x 32T block, thread = 4OC x 4T, cp.async pipeline ----
// Weights come pre-staged (g_wa/g_wb) so in-loop staging is pure 16B async copies.
template<int K, bool RELU, bool TROUT, bool INTERP, int OCB>
__global__ __launch_bounds__(256) void k_conv3(const float* __restrict__ in,
                                               const float* __restrict__ ws,
                                               const float* __restrict__ bias,
                                               float* __restrict__ out) {
    constexpr int P   = (K - 1) / 2;
    constexpr int ZW  = 32 + K - 1;          // 36 / 38
    constexpr int ZWP = (ZW + 3) & ~3;       // 36 / 40
    constexpr int WB  = 8 * K * 132;         // floats per chunk blob
    constexpr int WB4 = WB / 4;
    constexpr int WITER = (WB4 + 255) / 256;
    constexpr int NZ4 = (K + 6) / 4;         // 2 / 3
    extern __shared__ float smem[];
    float* wbuf0 = smem;
    float* wbuf1 = smem + WB;
    float* zbuf0 = smem + 2*WB;
    float* zbuf1 = smem + 2*WB + 8*ZWP;

    int tid = threadIdx.x;
    int tx = tid & 7, ty = tid >> 3;         // tx: 8 T-groups, ty: 32 OC-groups
    int t0 = blockIdx.x * 32, ob = blockIdx.y * 128, b = blockIdx.z;
    int OCt = OCB * 128;
    int o = ob + ty*4, tt = tx*4;

    float acc[4][4], sum[4][4];
    #pragma unroll
    for (int cIdx = 0; cIdx < 4; cIdx++)
        #pragma unroll
        for (int tl = 0; tl < 4; tl++) { acc[cIdx][tl] = 0.f; sum[cIdx][tl] = 0.f; }

    // ---- prologue: fetch chunk 0 ----
    float zt[2];
    {
        const float* src = ws + ((size_t)(blockIdx.y*64 + 0))*WB;
        uint32_t dst = (uint32_t)__cvta_generic_to_shared(wbuf0);
        #pragma unroll
        for (int it = 0; it < WITER; it++) {
            int e = tid + it*256;
            if (e < WB4)
                asm volatile("cp.async.ca.shared.global [%0], [%1], 16;"
                             :: "r"(dst + e*16), "l"((const void*)(src + e*4)));
        }
        asm volatile("cp.async.commit_group;");
        #pragma unroll
        for (int k = 0; k < 2; k++) {
            int e = tid + k*256;
            float v = 0.f;
            if (e < 8*ZW) {
                int i = e / ZW, u = e - i*ZW;
                int tg = t0 + u - P;
                if (tg >= 0 && tg < TT) {
                    if (INTERP) {
                        const float* row = g_z1 + ((size_t)b*HID + i)*TN;
                        float srcp = fmaxf(((float)tg + 0.5f)*0.5f - 0.5f, 0.0f);
                        int i0 = (int)srcp;
                        int i1 = min(i0 + 1, 3999);
                        float frac = srcp - (float)i0;
                        float v0 = row[i0 / 5];
                        float v1 = row[i1 / 5];
                        v = v0 * (1.0f - frac) + v1 * frac;
                    } else {
                        v = in[((size_t)b*HID + i)*TT + tg];
                    }
                }
            }
            zt[k] = v;
        }
        asm volatile("cp.async.wait_group 0;");
        #pragma unroll
        for (int k = 0; k < 2; k++) {
            int e = tid + k*256;
            if (e < 8*ZW) { int i = e / ZW, u = e - i*ZW; zbuf0[i*ZWP + u] = zt[k]; }
        }
        __syncthreads();
    }

    for (int c = 0; c < 64; c++) {
        const float* wb_ = (c & 1) ? wbuf1 : wbuf0;
        const float* zb_ = (c & 1) ? zbuf1 : zbuf0;
        float* wbn = (c & 1) ? wbuf0 : wbuf1;
        float* zbn = (c & 1) ? zbuf0 : zbuf1;
        if (c < 63) {
            // async-fetch next weights; issue next-z LDGs (consumed after compute)
            const float* src = ws + ((size_t)(blockIdx.y*64 + c + 1))*WB;
            uint32_t dst = (uint32_t)__cvta_generic_to_shared(wbn);
            #pragma unroll
            for (int it = 0; it < WITER; it++) {
                int e = tid + it*256;
                if (e < WB4)
                    asm volatile("cp.async.ca.shared.global [%0], [%1], 16;"
                                 :: "r"(dst + e*16), "l"((const void*)(src + e*4)));
            }
            asm volatile("cp.async.commit_group;");
            int ic0 = (c + 1) * 8;
            #pragma unroll
            for (int k = 0; k < 2; k++) {
                int e = tid + k*256;
                float v = 0.f;
                if (e < 8*ZW) {
                    int i = e / ZW, u = e - i*ZW;
                    int tg = t0 + u - P;
                    if (tg >= 0 && tg < TT) {
                        if (INTERP) {
                            const float* row = g_z1 + ((size_t)b*HID + ic0 + i)*TN;
                            float srcp = fmaxf(((float)tg + 0.5f)*0.5f - 0.5f, 0.0f);
                            int i0 = (int)srcp;
                            int i1 = min(i0 + 1, 3999);
                            float frac = srcp - (float)i0;
                            float v0 = row[i0 / 5];
                            float v1 = row[i1 / 5];
                            v = v0 * (1.0f - frac) + v1 * frac;
                        } else {
                            v = in[((size_t)b*HID + ic0 + i)*TT + tg];
                        }
                    }
                }
                zt[k] = v;
            }
        }
        // ---- compute chunk c ----
        #pragma unroll
        for (int i = 0; i < 8; i++) {
            float zl[NZ4 * 4];
            #pragma unroll
            for (int q = 0; q < NZ4; q++)
                *(float4*)&zl[q*4] = *(const float4*)&zb_[i*ZWP + tt + q*4];
            #pragma unroll
            for (int j = 0; j < K; j++) {
                float4 wv = *(const float4*)&wb_[(i*K + j)*132 + ty*4];
                #pragma unroll
                for (int tl = 0; tl < 4; tl++) {
                    float z = zl[tl + j];
                    acc[0][tl] += wv.x * z;
                    acc[1][tl] += wv.y * z;
                    acc[2][tl] += wv.z * z;
                    acc[3][tl] += wv.w * z;
                }
            }
        }
        if ((c & 3) == 3) {   // flush short fp32 chains (same cadence/order as before)
            #pragma unroll
            for (int cIdx = 0; cIdx < 4; cIdx++)
                #pragma unroll
                for (int tl = 0; tl < 4; tl++) { sum[cIdx][tl] += acc[cIdx][tl]; acc[cIdx][tl] = 0.f; }
        }
        if (c < 63) {
            asm volatile("cp.async.wait_group 0;");
            #pragma unroll
            for (int k = 0; k < 2; k++) {
                int e = tid + k*256;
                if (e < 8*ZW) { int i = e / ZW, u = e - i*ZW; zbn[i*ZWP + u] = zt[k]; }
            }
        }
        __syncthreads();
    }

    float resv[4][4];
    #pragma unroll
    for (int cIdx = 0; cIdx < 4; cIdx++) {
        float bv = bias[o + cIdx];
        #pragma unroll
        for (int tl = 0; tl < 4; tl++) {
            float v = sum[cIdx][tl] + bv;
            if (RELU) v = fmaxf(v, 0.f);
            resv[cIdx][tl] = v;
        }
    }
    if (!TROUT) {
        #pragma unroll
        for (int cIdx = 0; cIdx < 4; cIdx++) {
            float4 v = make_float4(resv[cIdx][0], resv[cIdx][1], resv[cIdx][2], resv[cIdx][3]);
            *(float4*)&out[((size_t)b*OCt + o + cIdx)*TT + t0 + tt] = v;
        }
    } else {
        #pragma unroll
        for (int tl = 0; tl < 4; tl++) {
            float4 v = make_float4(resv[0][tl], resv[1][tl], resv[2][tl], resv[3][tl]);
            *(float4*)&out[((size_t)b*TT + t0 + tt + tl)*OCt + o] = v;
        }
    }
}

// ---------------- codebook squared norms (double, stored fp32) ----------------
__global__ void k_cbnorm(const float* __restrict__ cb) {
    int id = blockIdx.x * 256 + threadIdx.x;
    if (id >= NQ * KCB) return;
    const float* r = cb + (size_t)id * LAT;
    double s = 0.0;
    for (int d = 0; d < LAT; d++) {
        double v = (double)r[d];
        s += v * v;
    }
    g_cbn[id] = (float)s;
}

// ---------------- residual VQ, one codebook per launch ----------------
__global__ __launch_bounds__(256) void k_vq(const float* __restrict__ cb_all, int qi) {
    extern __shared__ float sm[];
    float* rsm = sm;                      // 64 x 132
    float* csm = sm + 64*132;             // 128 x 132
    float* nsm = csm + 128*132;           // 128
    int tid = threadIdx.x, lane = tid & 31, w = tid >> 5;
    int row0 = blockIdx.x * 64;
    const float* src = (qi == 0) ? g_ze : g_res;
    for (int e = tid; e < 64*32; e += 256) {
        int lr = e >> 5, d4 = (e & 31) * 4;
        float4 v = *(const float4*)&src[(size_t)(row0 + lr)*LAT + d4];
        *(float4*)&rsm[lr*132 + d4] = v;
    }
    const float* cbq = cb_all + (size_t)qi * KCB * LAT;
    float bestv[8], secv[8]; int besti[8];
    #pragma unroll
    for (int rr = 0; rr < 8; rr++) { bestv[rr] = 3.4e38f; secv[rr] = 3.4e38f; besti[rr] = 0; }

    for (int cc = 0; cc < 8; cc++) {
        __syncthreads();
        for (int e = tid; e < 128*32; e += 256) {
            int k = e >> 5, d4 = (e & 31) * 4;
            float4 v = *(const float4*)&cbq[(size_t)(cc*128 + k)*LAT + d4];
            *(float4*)&csm[k*132 + d4] = v;
        }
        if (tid < 128) nsm[tid] = g_cbn[qi*KCB + cc*128 + tid];
        __syncthreads();
        float acc[8][4];
        #pragma unroll
        for (int rr = 0; rr < 8; rr++)
            #pragma unroll
            for (int c = 0; c < 4; c++) acc[rr][c] = 0.f;
        #pragma unroll 2
        for (int d = 0; d < 128; d += 4) {
            float4 cv[4];
            #pragma unroll
            for (int c = 0; c < 4; c++) cv[c] = *(const float4*)&csm[(lane*4 + c)*132 + d];
            #pragma unroll
            for (int rr = 0; rr < 8; rr++) {
                float4 rv = *(const float4*)&rsm[(w*8 + rr)*132 + d];
                #pragma unroll
                for (int c = 0; c < 4; c++) {
                    acc[rr][c] += rv.x*cv[c].x + rv.y*cv[c].y + rv.z*cv[c].z + rv.w*cv[c].w;
                }
            }
        }
        #pragma unroll
        for (int rr = 0; rr < 8; rr++) {
            #pragma unroll
            for (int c = 0; c < 4; c++) {
                float dist = nsm[lane*4 + c] - 2.0f * acc[rr][c];
                int idx = cc*128 + lane*4 + c;
                if (dist < bestv[rr]) { secv[rr] = bestv[rr]; bestv[rr] = dist; besti[rr] = idx; }
                else if (dist < secv[rr]) { secv[rr] = dist; }
            }
        }
    }

    double dq_local = 0.0;
    for (int rr = 0; rr < 8; rr++) {
        float v1 = bestv[rr]; int i1 = besti[rr]; float v2 = secv[rr];
        #pragma unroll
        for (int off = 16; off > 0; off >>= 1) {
            float ov1 = __shfl_xor_sync(0xffffffffu, v1, off);
            int   oi1 = __shfl_xor_sync(0xffffffffu, i1, off);
            float ov2 = __shfl_xor_sync(0xffffffffu, v2, off);
            if (ov1 < v1 || (ov1 == v1 && oi1 < i1)) {
                v2 = fminf(v1, ov2);
                v1 = ov1; i1 = oi1;
            } else {
                v2 = fminf(v2, ov1);
            }
        }
        int ix = i1;
        int rloc = w*8 + rr;
        // ---- exact fp64 rescore when the fp32 margin is too small ----
        if (v2 - v1 < RESCORE_TAU) {
            double bd = 1e300; int bi = 0x7fffffff;
            for (int kk = 0; kk < 32; kk++) {
                int k = kk*32 + lane;
                const float* cr = cbq + (size_t)k * LAT;
                double s = 0.0;
                for (int d = 0; d < 128; d++) {
                    double cd = (double)cr[d];
                    double rd = (double)rsm[rloc*132 + d];
                    s += cd*cd - 2.0*rd*cd;
                }
                if (s < bd || (s == bd && k < bi)) { bd = s; bi = k; }
            }
            #pragma unroll
            for (int off = 16; off > 0; off >>= 1) {
                double ob = __shfl_xor_sync(0xffffffffu, bd, off);
                int    oi = __shfl_xor_sync(0xffffffffu, bi, off);
                if (ob < bd || (ob == bd && oi < bi)) { bd = ob; bi = oi; }
            }
            ix = bi;
        }

        int r = row0 + rloc;
        const float* q = cbq + (size_t)ix * LAT;
        float4 qv = *(const float4*)&q[lane*4];
        float4 rv = *(const float4*)&rsm[rloc*132 + lane*4];
        double r2 = (double)rv.x*rv.x + (double)rv.y*rv.y + (double)rv.z*rv.z + (double)rv.w*rv.w;
        double q2 = (double)qv.x*qv.x + (double)qv.y*qv.y + (double)qv.z*qv.z + (double)qv.w*qv.w;
        double rq = (double)rv.x*qv.x + (double)rv.y*qv.y + (double)rv.z*qv.z + (double)rv.w*qv.w;
        double dxd = (double)qv.x - rv.x, dyd = (double)qv.y - rv.y;
        double dzd = (double)qv.z - rv.z, dwd = (double)qv.w - rv.w;
        double dq = dxd*dxd + dyd*dyd + dzd*dzd + dwd*dwd;
        #pragma unroll
        for (int off = 16; off > 0; off >>= 1) {
            r2 += __shfl_xor_sync(0xffffffffu, r2, off);
            q2 += __shfl_xor_sync(0xffffffffu, q2, off);
            rq += __shfl_xor_sync(0xffffffffu, rq, off);
            dq += __shfl_xor_sync(0xffffffffu, dq, off);
        }
        double ns = sqrt(r2), nt = sqrt(q2);
        double ins = 1.0 / (ns + 1e-12), intq = 1.0 / (nt + 1e-12);
        double ru = r2 * ins;                                        // r . u
        double ss2 = r2*ins*ins + 2.0*rq*ins*intq + q2*intq*intq;    // ||u+qh||^2
        double wn = sqrt(ss2);
        double iw = 1.0 / (wn + 1e-12);
        double rs = ru + rq * intq;                                  // r . (u+qh)
        double rw = rs * iw;                                         // r . w
        double scale = nt * ins;
        float4 qrf;
        {
            double sx = (double)rv.x*ins + (double)qv.x*intq;
            double sy = (double)rv.y*ins + (double)qv.y*intq;
            double sz = (double)rv.z*ins + (double)qv.z*intq;
            double sw = (double)rv.w*ins + (double)qv.w*intq;
            qrf.x = (float)(((double)rv.x - 2.0*rw*(sx*iw) + 2.0*ru*((double)qv.x*intq)) * scale);
            qrf.y = (float)(((double)rv.y - 2.0*rw*(sy*iw) + 2.0*ru*((double)qv.y*intq)) * scale);
            qrf.z = (float)(((double)rv.z - 2.0*rw*(sz*iw) + 2.0*ru*((double)qv.z*intq)) * scale);
            qrf.w = (float)(((double)rv.w - 2.0*rw*(sw*iw) + 2.0*ru*((double)qv.w*intq)) * scale);
        }
        size_t base = (size_t)r * LAT + lane*4;
        if (qi == 0) {
            *(float4*)&g_qout[base] = qrf;
        } else {
            float4 old = *(const float4*)&g_qout[base];
            old.x += qrf.x; old.y += qrf.y; old.z += qrf.z; old.w += qrf.w;
            *(float4*)&g_qout[base] = old;
        }
        if (qi < 3) {
            float4 nr = make_float4(rv.x - qrf.x, rv.y - qrf.y, rv.z - qrf.z, rv.w - qrf.w);
            *(float4*)&g_res[base] = nr;
        }
        if (lane == 0) {
            g_codes[r*NQ + qi] = ix;
            dq_local += dq;
        }
    }
    if (lane == 0) atomicAdd(&g_acc[qi], dq_local);
}

// ---------------- smooth loss ----------------
__global__ void k_smooth() {
    int idx = blockIdx.x * 256 + threadIdx.x;
    int cnt = 0;
    if (idx < BB * (TT - 1)) {
        int b = idx / (TT - 1), t = idx % (TT - 1);
        int a = g_codes[(b*TT + t)*NQ + 0];
        int c = g_codes[(b*TT + t + 1)*NQ + 0];
        cnt = (a != c) ? 1 : 0;
    }
    __shared__ int red[256];
    red[threadIdx.x] = cnt;
    __syncthreads();
    for (int s = 128; s > 0; s >>= 1) {
        if (threadIdx.x < s) red[threadIdx.x] += red[threadIdx.x + s];
        __syncthreads();
    }
    if (threadIdx.x == 0 && red[0]) atomicAdd(&g_acc[4], (double)red[0]);
}

// ---------------- fused decoder (dec1 + relu + dec2 + recon loss), 8 chunks/block ----------------
__global__ __launch_bounds__(256) void k_dec(const float* __restrict__ b1,
                                             const float* __restrict__ b2) {
    extern __shared__ float sm[];
    float* insm = sm;                  // 8 * 660
    float* hsm  = sm + 8*660;          // 8 * 2560
    float* red  = hsm + 8*2560;        // 256
    int tid = threadIdx.x;
    int g0 = blockIdx.x * 8;

    for (int e = tid; e < 8*660; e += 256) {
        int ch = e / 660, rem = e % 660;
        int c = rem / 5, l = rem % 5;
        int g = g0 + ch;
        int b = g / COUNT_DEC, n = g % COUNT_DEC;
        int t = n*5 + l;
        float v;
        if (c < 128) v = g_qout[((size_t)b*TT + t)*LAT + c];
        else         v = (float)g_codes[(b*TT + t)*NQ + (c - 128)];
        insm[ch*660 + c*5 + l] = v;
    }
    __syncthreads();

    // phase 1: dec1 conv K=5 pad 2 over L=5, relu
    for (int op = 0; op < 2; op++) {
        int o = tid + op*256;
        float acc[8][5];
        float bbv = b1[o];
        #pragma unroll
        for (int ch = 0; ch < 8; ch++)
            #pragma unroll
            for (int l = 0; l < 5; l++) acc[ch][l] = bbv;
        for (int c = 0; c < 132; c++) {
            float inr[8][5];
            #pragma unroll
            for (int ch = 0; ch < 8; ch++)
                #pragma unroll
                for (int l = 0; l < 5; l++) inr[ch][l] = insm[ch*660 + c*5 + l];
            #pragma unroll
            for (int j = 0; j < 5; j++) {
                float wv = g_w1t[(c*5 + j)*512 + o];
                #pragma unroll
                for (int l = 0; l < 5; l++) {
                    int p = l + j - 2;
                    if (p >= 0 && p < 5) {
                        #pragma unroll
                        for (int ch = 0; ch < 8; ch++) acc[ch][l] += wv * inr[ch][p];
                    }
                }
            }
        }
        #pragma unroll
        for (int ch = 0; ch < 8; ch++)
            #pragma unroll
            for (int l = 0; l < 5; l++)
                hsm[ch*2560 + o*5 + l] = fmaxf(acc[ch][l], 0.f);
    }
    __syncthreads();

    // phase 2: dec2 conv K=3 pad 1, subtract true chunk, square
    int o2 = tid & 127, gp = tid >> 7;
    float acc2[4][5];
    float bb2 = b2[o2];
    #pragma unroll
    for (int cc = 0; cc < 4; cc++)
        #pragma unroll
        for (int l = 0; l < 5; l++) acc2[cc][l] = bb2;
    for (int c = 0; c < 512; c++) {
        float hr[4][5];
        #pragma unroll
        for (int cc = 0; cc < 4; cc++)
            #pragma unroll
            for (int l = 0; l < 5; l++) hr[cc][l] = hsm[(gp*4 + cc)*2560 + c*5 + l];
        #pragma unroll
        for (int j = 0; j < 3; j++) {
            float wv = g_w2t[(c*3 + j)*128 + o2];
            #pragma unroll
            for (int l = 0; l < 5; l++) {
                int p = l + j - 1;
                if (p >= 0 && p < 5) {
                    #pragma unroll
                    for (int cc = 0; cc < 4; cc++) acc2[cc][l] += wv * hr[cc][p];
                }
            }
        }
    }
    float lsum = 0.f;
    #pragma unroll
    for (int cc = 0; cc < 4; cc++) {
        int g = g0 + gp*4 + cc;
        int b = g / COUNT_DEC, n = g % COUNT_DEC;
        #pragma unroll
        for (int l = 0; l < 5; l++) {
            int t = (n + 1)*5 + l;
            float d = acc2[cc][l] - g_qout[((size_t)b*TT + t)*LAT + o2];
            lsum += d*d;
        }
    }
    red[tid] = lsum;
    __syncthreads();
    for (int s = 128; s > 0; s >>= 1) {
        if (tid < s) red[tid] += red[tid + s];
        __syncthreads();
    }
    if (tid == 0) atomicAdd(&g_acc[5], (double)red[0]);
}

// ---------------- outputs ----------------
__global__ void k_codes_out(float* __restrict__ out, int out_size) {
    int i = blockIdx.x * 256 + threadIdx.x;
    if (i < BB*TT*NQ && i < out_size) out[i] = (float)g_codes[i];
}

__global__ void k_final(float* __restrict__ out, int out_size) {
    if (threadIdx.x != 0 || blockIdx.x != 0) return;
    double nv = (double)BB * TT * LAT;                  // 16,384,000
    double vq = (g_acc[0]/nv + g_acc[1]/nv + g_acc[2]/nv + g_acc[3]/nv) / 4.0;
    double recon = g_acc[5] / ((double)NCHUNKS * LAT * 5);
    double smooth = g_acc[4] / ((double)BB * (TT - 1));
    double loss = recon * 1.0 + vq * 1.0 + smooth * 0.1;
    int base = BB*TT*NQ;
    if (base + 0 < out_size) out[base + 0] = (float)loss;
    if (base + 1 < out_size) out[base + 1] = (float)recon;
    if (base + 2 < out_size) out[base + 2] = (float)vq;
    if (base + 3 < out_size) out[base + 3] = (float)smooth;
}

// ---------------- launch ----------------
// Launch order keeps enc2a (k_conv3<5>) at index 3, where ncu samples.
extern "C" void kernel_launch(void* const* d_in, const int* in_sizes, int n_in,
                              void* d_out, int out_size) {
    const float* traj = (const float*)d_in[0];
    // d_in[1] = masks (unused by reference forward)
    const float* e1w  = (const float*)d_in[2];
    const float* e1b  = (const float*)d_in[3];
    const float* e2aw = (const float*)d_in[4];
    const float* e2ab = (const float*)d_in[5];
    const float* e2bw = (const float*)d_in[6];
    const float* e2bb = (const float*)d_in[7];
    const float* d1w  = (const float*)d_in[8];
    const float* d1b  = (const float*)d_in[9];
    const float* d2w  = (const float*)d_in[10];
    const float* d2b  = (const float*)d_in[11];
    const float* cb   = (const float*)d_in[12];
    float* out = (float*)d_out;

    const int VQ_SMEM  = (64*132 + 128*132 + 128) * 4;        // 101,888 B
    const int DEC_SMEM = (8*660 + 8*2560 + 256) * 4;          // 104,064 B
    const int CA_SMEM  = (2*(8*5*132) + 2*8*36) * 4;          // 44,544 B
    const int CB_SMEM  = (2*(8*7*132) + 2*8*40) * 4;          // 61,696 B
    cudaFuncSetAttribute(k_vq,  cudaFuncAttributeMaxDynamicSharedMemorySize, VQ_SMEM);
    cudaFuncSetAttribute(k_dec, cudaFuncAttributeMaxDynamicSharedMemorySize, DEC_SMEM);
    cudaFuncSetAttribute((const void*)k_conv3<5, true, false, true, 4>,
                         cudaFuncAttributeMaxDynamicSharedMemorySize, CA_SMEM);
    cudaFuncSetAttribute((const void*)k_conv3<7, false, true, false, 1>,
                         cudaFuncAttributeMaxDynamicSharedMemorySize, CB_SMEM);

    void *p_z3 = nullptr, *p_ze = nullptr, *p_wa = nullptr, *p_wb = nullptr;
    cudaGetSymbolAddress(&p_z3, g_z3);
    cudaGetSymbolAddress(&p_ze, g_ze);
    cudaGetSymbolAddress(&p_wa, g_wa);
    cudaGetSymbolAddress(&p_wb, g_wb);

    k_zero_acc<<<1, 32>>>();                                               // 0
    k_enc1<<<dim3(TN/16, BB), 256>>>(traj, e1w, e1b);                      // 1
    k_wstage<<<(4*64*8*5*128)/256, 256>>>(e2aw, (float*)p_wa, 5, 4);       // 2
    // enc2a: 512->512, K=5, relu, interp-fused input                      // 3 <- ncu target
    k_conv3<5, true, false, true, 4><<<dim3(TT/32, 4, BB), 256, CA_SMEM>>>(
        nullptr, (const float*)p_wa, e2ab, (float*)p_z3);
    k_wstage<<<(1*64*8*7*128)/256, 256>>>(e2bw, (float*)p_wb, 7, 1);       // 4
    // enc2b: 512->128, K=7, transposed out (B,T,128)                      // 5
    k_conv3<7, false, true, false, 1><<<dim3(TT/32, 1, BB), 256, CB_SMEM>>>(
        (const float*)p_z3, (const float*)p_wb, e2bb, (float*)p_ze);
    k_tw1<<<(512*660 + 255)/256, 256>>>(d1w);                              // 6
    k_tw2<<<(128*1536 + 255)/256, 256>>>(d2w);                             // 7
    k_cbnorm<<<(NQ*KCB)/256, 256>>>(cb);                                   // 8
    for (int qi = 0; qi < NQ; qi++) {
        k_vq<<<(BB*TT)/64, 256, VQ_SMEM>>>(cb, qi);                        // 9-12
    }
    k_smooth<<<(BB*(TT-1) + 255)/256, 256>>>();                            // 13
    k_dec<<<NCHUNKS/8, 256, DEC_SMEM>>>(d1b, d2b);                         // 14
    k_codes_out<<<(BB*TT*NQ)/256, 256>>>(out, out_size);                   // 15
    k_final<<<1, 32>>>(out, out_size);                                     // 16
}

// round 11
// speedup vs baseline: 1.5629x; 1.1086x over previous
#include <cuda_runtime.h>
#include <cuda_bf16.h>
#include <stdint.h>
#include <math.h>

#define BB   16
#define TT   8000
#define TN   800
#define HID  512
#define LAT  128
#define KCB  1024
#define NQ   4
#define COUNT_DEC 1599
#define NCHUNKS   25584   // BB * COUNT_DEC
#define RESCORE_TAU 4e-3f

// ---------------- scratch (device globals; no allocation allowed) ----------------
__device__ float g_z1[BB*HID*TN];        // enc1 out (B,512,800)
__device__ float g_z3[(size_t)BB*HID*TT];// enc2a out (B,512,8000)
__device__ float g_ze[(size_t)BB*TT*LAT];// enc2b out, transposed (B,T,128)
__device__ float g_res[(size_t)BB*TT*LAT];
__device__ float g_qout[(size_t)BB*TT*LAT];
__device__ int   g_codes[BB*TT*NQ];
__device__ float g_cbn[NQ*KCB];
__device__ float g_w1t[132*5*512];       // dec1 weights transposed
__device__ float g_w2t[512*3*128];       // dec2 weights transposed
__device__ float g_wb[1*64*8*7*132];     // enc2b weights pre-staged (scalar conv3)
// enc2a HMMA weight image: per (ocb,chunk): [limb(2)][oc(128)][kpad(88)] bf16
__device__ __nv_bfloat16 g_wh[4*32*22528];
__device__ double g_acc[8];  // [0..3] vq sums, [4] smooth count, [5] recon sum

__device__ __forceinline__ uint32_t pkbf(__nv_bfloat16 x, __nv_bfloat16 y) {
    return (uint32_t)__bfloat16_as_ushort(x) | ((uint32_t)__bfloat16_as_ushort(y) << 16);
}

#define MMA16816(C, A, B0, B1) \
    asm volatile("mma.sync.aligned.m16n8k16.row.col.f32.bf16.bf16.f32 " \
        "{%0,%1,%2,%3}, {%4,%5,%6,%7}, {%8,%9}, {%0,%1,%2,%3};" \
        : "+f"((C)[0]), "+f"((C)[1]), "+f"((C)[2]), "+f"((C)[3]) \
        : "r"((A)[0]), "r"((A)[1]), "r"((A)[2]), "r"((A)[3]), "r"(B0), "r"(B1))

// ---------------- tiny utility kernels ----------------
__global__ void k_zero_acc() {
    if (threadIdx.x < 8) g_acc[threadIdx.x] = 0.0;
}
__global__ void k_tw1(const float* __restrict__ w1) {
    int idx = blockIdx.x * 256 + threadIdx.x;
    if (idx >= 512*660) return;
    int o = idx / 660, r = idx % 660;
    g_w1t[r*512 + o] = w1[idx];
}
__global__ void k_tw2(const float* __restrict__ w2) {
    int idx = blockIdx.x * 256 + threadIdx.x;
    if (idx >= 128*1536) return;
    int o = idx / 1536, r = idx % 1536;
    g_w2t[r*128 + o] = w2[idx];
}
__global__ void k_wstage(const float* __restrict__ wt, float* __restrict__ dst,
                         int K, int OCB) {
    int idx = blockIdx.x * 256 + threadIdx.x;
    int total = OCB * 64 * 8 * K * 128;
    if (idx >= total) return;
    int ol = idx & 127;
    int r  = idx >> 7;
    int j  = r % K;  r /= K;
    int i  = r & 7;  r >>= 3;
    int chunk = r & 63;
    int ocb   = r >> 6;
    dst[((size_t)(ocb*64 + chunk))*(8*K*132) + (i*K + j)*132 + ol] =
        wt[((size_t)(ocb*128 + ol)*512 + chunk*8 + i)*K + j];
}

// enc2a weight prep: im2col k = icl*5 + j (icl in 16-ic chunk), 2 bf16 limbs
__global__ void k_wprep2(const float* __restrict__ wt) {
    int idx = blockIdx.x * 256 + threadIdx.x;
    if (idx >= 4*32*128*88) return;
    int kp = idx % 88; int r = idx / 88;
    int oc = r % 128; r /= 128;
    int ch = r % 32; int ocb = r / 32;
    float w = 0.f;
    if (kp < 80) {
        int icl = kp / 5, j = kp - icl*5;
        w = wt[(((size_t)(ocb*128 + oc))*512 + ch*16 + icl)*5 + j];
    }
    __nv_bfloat16 h = __float2bfloat16(w);
    __nv_bfloat16 l = __float2bfloat16(w - __bfloat162float(h));
    size_t base = (size_t)(ocb*32 + ch)*22528 + (size_t)oc*88 + kp;
    g_wh[base] = h;
    g_wh[base + 11264] = l;
}

// ---------------- enc1: (B,20,800) -> relu conv K=3 -> (B,512,800) ----------------
__global__ __launch_bounds__(256) void k_enc1(const float* __restrict__ traj,
                                              const float* __restrict__ w,
                                              const float* __restrict__ bias) {
    __shared__ float xs[20][18];
    int b = blockIdx.y, t0 = blockIdx.x * 16;
    int tid = threadIdx.x;
    for (int e = tid; e < 20*18; e += 256) {
        int i = e / 18, u = e % 18;
        int tg = t0 + u - 1;
        float v = 0.f;
        if (tg >= 0 && tg < TN) v = traj[((size_t)b*2 + (i/10))*TT + tg*10 + (i%10)];
        xs[i][u] = v;
    }
    __syncthreads();
    int o0 = tid, o1 = tid + 256;
    float acc0[16], acc1[16];
    float b0 = bias[o0], b1v = bias[o1];
    #pragma unroll
    for (int t = 0; t < 16; t++) { acc0[t] = 0.f; acc1[t] = 0.f; }
    for (int i = 0; i < 20; i++) {
        #pragma unroll
        for (int j = 0; j < 3; j++) {
            float w0 = w[(o0*20 + i)*3 + j];
            float w1 = w[(o1*20 + i)*3 + j];
            #pragma unroll
            for (int t = 0; t < 16; t++) {
                float x = xs[i][t + j];
                acc0[t] += w0 * x;
                acc1[t] += w1 * x;
            }
        }
    }
    #pragma unroll
    for (int t = 0; t < 16; t++) {
        g_z1[((size_t)b*HID + o0)*TN + t0 + t] = fmaxf(acc0[t] + b0, 0.f);
        g_z1[((size_t)b*HID + o1)*TN + t0 + t] = fmaxf(acc1[t] + b1v, 0.f);
    }
}

// ---------------- enc2a via mma.sync bf16 2-limb (HMMA) ----------------
// grid (125 t-tiles of 64, 4 ocb, 16 b), 256 threads = 8 warps.
// Block tile 128 OC x 64 T; warp (wm = warp&3, wn = warp>>2): 32 OC x 32 T.
__global__ __launch_bounds__(256) void k_enc2a_hmma(
    const __nv_bfloat16* __restrict__ wh, const float* __restrict__ bias) {
    extern __shared__ char smem[];
    __nv_bfloat16* ash = (__nv_bfloat16*)smem;          // [2][128][88] bf16
    float* zr = (float*)(smem + 45056);                 // [16][68] f32
    int tid = threadIdx.x, lane = tid & 31, warp = tid >> 5;
    int wm = warp & 3, wn = warp >> 2;
    int t0 = blockIdx.x * 64, ob = blockIdx.y * 128, b = blockIdx.z;

    float c[2][4][4];
    #pragma unroll
    for (int i = 0; i < 2; i++)
        #pragma unroll
        for (int nt = 0; nt < 4; nt++)
            #pragma unroll
            for (int q = 0; q < 4; q++) c[i][nt][q] = 0.f;

    uint32_t adst = (uint32_t)__cvta_generic_to_shared(ash);

    for (int ch = 0; ch < 32; ch++) {
        __syncthreads();   // protect prior-iteration smem reads
        // A limbs via cp.async (pre-imaged contiguous blob: 45056 B)
        {
            const __nv_bfloat16* src = wh + (size_t)(blockIdx.y*32 + ch) * 22528;
            #pragma unroll
            for (int it = 0; it < 11; it++) {
                int e = tid + it*256;
                asm volatile("cp.async.ca.shared.global [%0], [%1], 16;"
                             :: "r"(adst + e*16), "l"((const void*)(src + e*8)));
            }
            asm volatile("cp.async.commit_group;");
        }
        // z interp staging: zr[icl][u] = z[ch*16+icl][t0+u-2]
        {
            int ic0 = ch * 16;
            for (int e = tid; e < 1088; e += 256) {
                int icl = e / 68, u = e - icl*68;
                int tg = t0 + u - 2;
                float v = 0.f;
                if (tg >= 0 && tg < TT) {
                    const float* row = g_z1 + ((size_t)b*HID + ic0 + icl)*TN;
                    float srcp = fmaxf(((float)tg + 0.5f)*0.5f - 0.5f, 0.0f);
                    int i0 = (int)srcp;
                    int i1 = min(i0 + 1, 3999);
                    float frac = srcp - (float)i0;
                    v = row[i0/5]*(1.0f - frac) + row[i1/5]*frac;
                }
                zr[e] = v;
            }
        }
        asm volatile("cp.async.wait_group 0;");
        __syncthreads();

        #pragma unroll
        for (int ks = 0; ks < 5; ks++) {
            int kb = ks*16 + (lane & 3)*2;       // lane's k base within chunk
            // --- B fragments (4 n-tiles, 2 limbs) from fp32 zr ---
            uint32_t bL1[4][2], bL2[4][2];
            #pragma unroll
            for (int nt = 0; nt < 4; nt++) {
                int n = wn*32 + nt*8 + (lane >> 2);
                float zv[4];
                #pragma unroll
                for (int q = 0; q < 4; q++) {
                    int kl = kb + (q & 1) + ((q & 2) ? 8 : 0);
                    int icl = kl / 5, j = kl - icl*5;
                    zv[q] = zr[icl*68 + n + j];
                }
                __nv_bfloat16 h[4], l[4];
                #pragma unroll
                for (int q = 0; q < 4; q++) {
                    h[q] = __float2bfloat16(zv[q]);
                    l[q] = __float2bfloat16(zv[q] - __bfloat162float(h[q]));
                }
                bL1[nt][0] = pkbf(h[0], h[1]); bL1[nt][1] = pkbf(h[2], h[3]);
                bL2[nt][0] = pkbf(l[0], l[1]); bL2[nt][1] = pkbf(l[2], l[3]);
            }
            // --- A fragments (2 m-tiles x 2 limbs), direct LDS.32 ---
            uint32_t aF[2][2][4];
            #pragma unroll
            for (int i = 0; i < 2; i++) {
                int m = wm*32 + i*16 + (lane >> 2);
                #pragma unroll
                for (int lb = 0; lb < 2; lb++) {
                    const __nv_bfloat16* base = ash + lb*11264;
                    aF[i][lb][0] = *(const uint32_t*)(base + (size_t)m*88 + kb);
                    aF[i][lb][1] = *(const uint32_t*)(base + (size_t)(m + 8)*88 + kb);
                    aF[i][lb][2] = *(const uint32_t*)(base + (size_t)m*88 + kb + 8);
                    aF[i][lb][3] = *(const uint32_t*)(base + (size_t)(m + 8)*88 + kb + 8);
                }
            }
            // --- 3-product limb MMAs ---
            #pragma unroll
            for (int i = 0; i < 2; i++) {
                #pragma unroll
                for (int nt = 0; nt < 4; nt++) {
                    MMA16816(c[i][nt], aF[i][0], bL1[nt][0], bL1[nt][1]);
                    MMA16816(c[i][nt], aF[i][0], bL2[nt][0], bL2[nt][1]);
                    MMA16816(c[i][nt], aF[i][1], bL1[nt][0], bL1[nt][1]);
                }
            }
        }
    }

    // epilogue: bias + relu, write g_z3[b][oc][t]
    #pragma unroll
    for (int i = 0; i < 2; i++) {
        int oc0 = ob + wm*32 + i*16 + (lane >> 2);
        float bv0 = bias[oc0], bv1 = bias[oc0 + 8];
        #pragma unroll
        for (int nt = 0; nt < 4; nt++) {
            int t = t0 + wn*32 + nt*8 + (lane & 3)*2;
            float2 v0, v1;
            v0.x = fmaxf(c[i][nt][0] + bv0, 0.f);
            v0.y = fmaxf(c[i][nt][1] + bv0, 0.f);
            v1.x = fmaxf(c[i][nt][2] + bv1, 0.f);
            v1.y = fmaxf(c[i][nt][3] + bv1, 0.f);
            *(float2*)&g_z3[((size_t)b*HID + oc0)*TT + t]     = v0;
            *(float2*)&g_z3[((size_t)b*HID + oc0 + 8)*TT + t] = v1;
        }
    }
}

// ---------------- conv3 scalar path (enc2b), unchanged ----------------
template<int K, bool RELU, bool TROUT, bool INTERP, int OCB>
__global__ __launch_bounds__(256) void k_conv3(const float* __restrict__ in,
                                               const float* __restrict__ ws,
                                               const float* __restrict__ bias,
                                               float* __restrict__ out) {
    constexpr int P   = (K - 1) / 2;
    constexpr int ZW  = 32 + K - 1;
    constexpr int ZWP = (ZW + 3) & ~3;
    constexpr int WB  = 8 * K * 132;
    constexpr int WB4 = WB / 4;
    constexpr int WITER = (WB4 + 255) / 256;
    constexpr int NZ4 = (K + 6) / 4;
    extern __shared__ float smemf[];
    float* wbuf0 = smemf;
    float* wbuf1 = smemf + WB;
    float* zbuf0 = smemf + 2*WB;
    float* zbuf1 = smemf + 2*WB + 8*ZWP;

    int tid = threadIdx.x;
    int tx = tid & 7, ty = tid >> 3;
    int t0 = blockIdx.x * 32, ob = blockIdx.y * 128, b = blockIdx.z;
    int OCt = OCB * 128;
    int o = ob + ty*4, tt = tx*4;

    float acc[4][4], sum[4][4];
    #pragma unroll
    for (int cIdx = 0; cIdx < 4; cIdx++)
        #pragma unroll
        for (int tl = 0; tl < 4; tl++) { acc[cIdx][tl] = 0.f; sum[cIdx][tl] = 0.f; }

    float zt[2];
    {
        const float* src = ws + ((size_t)(blockIdx.y*64 + 0))*WB;
        uint32_t dst = (uint32_t)__cvta_generic_to_shared(wbuf0);
        #pragma unroll
        for (int it = 0; it < WITER; it++) {
            int e = tid + it*256;
            if (e < WB4)
                asm volatile("cp.async.ca.shared.global [%0], [%1], 16;"
                             :: "r"(dst + e*16), "l"((const void*)(src + e*4)));
        }
        asm volatile("cp.async.commit_group;");
        #pragma unroll
        for (int k = 0; k < 2; k++) {
            int e = tid + k*256;
            float v = 0.f;
            if (e < 8*ZW) {
                int i = e / ZW, u = e - i*ZW;
                int tg = t0 + u - P;
                if (tg >= 0 && tg < TT) {
                    if (INTERP) {
                        const float* row = g_z1 + ((size_t)b*HID + i)*TN;
                        float srcp = fmaxf(((float)tg + 0.5f)*0.5f - 0.5f, 0.0f);
                        int i0 = (int)srcp;
                        int i1 = min(i0 + 1, 3999);
                        float frac = srcp - (float)i0;
                        v = row[i0/5] * (1.0f - frac) + row[i1/5] * frac;
                    } else {
                        v = in[((size_t)b*HID + i)*TT + tg];
                    }
                }
            }
            zt[k] = v;
        }
        asm volatile("cp.async.wait_group 0;");
        #pragma unroll
        for (int k = 0; k < 2; k++) {
            int e = tid + k*256;
            if (e < 8*ZW) { int i = e / ZW, u = e - i*ZW; zbuf0[i*ZWP + u] = zt[k]; }
        }
        __syncthreads();
    }

    for (int c = 0; c < 64; c++) {
        const float* wb_ = (c & 1) ? wbuf1 : wbuf0;
        const float* zb_ = (c & 1) ? zbuf1 : zbuf0;
        float* wbn = (c & 1) ? wbuf0 : wbuf1;
        float* zbn = (c & 1) ? zbuf0 : zbuf1;
        if (c < 63) {
            const float* src = ws + ((size_t)(blockIdx.y*64 + c + 1))*WB;
            uint32_t dst = (uint32_t)__cvta_generic_to_shared(wbn);
            #pragma unroll
            for (int it = 0; it < WITER; it++) {
                int e = tid + it*256;
                if (e < WB4)
                    asm volatile("cp.async.ca.shared.global [%0], [%1], 16;"
                                 :: "r"(dst + e*16), "l"((const void*)(src + e*4)));
            }
            asm volatile("cp.async.commit_group;");
            int ic0 = (c + 1) * 8;
            #pragma unroll
            for (int k = 0; k < 2; k++) {
                int e = tid + k*256;
                float v = 0.f;
                if (e < 8*ZW) {
                    int i = e / ZW, u = e - i*ZW;
                    int tg = t0 + u - P;
                    if (tg >= 0 && tg < TT) {
                        if (INTERP) {
                            const float* row = g_z1 + ((size_t)b*HID + ic0 + i)*TN;
                            float srcp = fmaxf(((float)tg + 0.5f)*0.5f - 0.5f, 0.0f);
                            int i0 = (int)srcp;
                            int i1 = min(i0 + 1, 3999);
                            float frac = srcp - (float)i0;
                            v = row[i0/5] * (1.0f - frac) + row[i1/5] * frac;
                        } else {
                            v = in[((size_t)b*HID + ic0 + i)*TT + tg];
                        }
                    }
                }
                zt[k] = v;
            }
        }
        #pragma unroll
        for (int i = 0; i < 8; i++) {
            float zl[NZ4 * 4];
            #pragma unroll
            for (int q = 0; q < NZ4; q++)
                *(float4*)&zl[q*4] = *(const float4*)&zb_[i*ZWP + tt + q*4];
            #pragma unroll
            for (int j = 0; j < K; j++) {
                float4 wv = *(const float4*)&wb_[(i*K + j)*132 + ty*4];
                #pragma unroll
                for (int tl = 0; tl < 4; tl++) {
                    float z = zl[tl + j];
                    acc[0][tl] += wv.x * z;
                    acc[1][tl] += wv.y * z;
                    acc[2][tl] += wv.z * z;
                    acc[3][tl] += wv.w * z;
                }
            }
        }
        if ((c & 3) == 3) {
            #pragma unroll
            for (int cIdx = 0; cIdx < 4; cIdx++)
                #pragma unroll
                for (int tl = 0; tl < 4; tl++) { sum[cIdx][tl] += acc[cIdx][tl]; acc[cIdx][tl] = 0.f; }
        }
        if (c < 63) {
            asm volatile("cp.async.wait_group 0;");
            #pragma unroll
            for (int k = 0; k < 2; k++) {
                int e = tid + k*256;
                if (e < 8*ZW) { int i = e / ZW, u = e - i*ZW; zbn[i*ZWP + u] = zt[k]; }
            }
        }
        __syncthreads();
    }

    float resv[4][4];
    #pragma unroll
    for (int cIdx = 0; cIdx < 4; cIdx++) {
        float bv = bias[o + cIdx];
        #pragma unroll
        for (int tl = 0; tl < 4; tl++) {
            float v = sum[cIdx][tl] + bv;
            if (RELU) v = fmaxf(v, 0.f);
            resv[cIdx][tl] = v;
        }
    }
    if (!TROUT) {
        #pragma unroll
        for (int cIdx = 0; cIdx < 4; cIdx++) {
            float4 v = make_float4(resv[cIdx][0], resv[cIdx][1], resv[cIdx][2], resv[cIdx][3]);
            *(float4*)&out[((size_t)b*OCt + o + cIdx)*TT + t0 + tt] = v;
        }
    } else {
        #pragma unroll
        for (int tl = 0; tl < 4; tl++) {
            float4 v = make_float4(resv[0][tl], resv[1][tl], resv[2][tl], resv[3][tl]);
            *(float4*)&out[((size_t)b*TT + t0 + tt + tl)*OCt + o] = v;
        }
    }
}

// ---------------- codebook squared norms ----------------
__global__ void k_cbnorm(const float* __restrict__ cb) {
    int id = blockIdx.x * 256 + threadIdx.x;
    if (id >= NQ * KCB) return;
    const float* r = cb + (size_t)id * LAT;
    double s = 0.0;
    for (int d = 0; d < LAT; d++) {
        double v = (double)r[d];
        s += v * v;
    }
    g_cbn[id] = (float)s;
}

// ---------------- residual VQ (unchanged) ----------------
__global__ __launch_bounds__(256) void k_vq(const float* __restrict__ cb_all, int qi) {
    extern __shared__ float sm[];
    float* rsm = sm;
    float* csm = sm + 64*132;
    float* nsm = csm + 128*132;
    int tid = threadIdx.x, lane = tid & 31, w = tid >> 5;
    int row0 = blockIdx.x * 64;
    const float* src = (qi == 0) ? g_ze : g_res;
    for (int e = tid; e < 64*32; e += 256) {
        int lr = e >> 5, d4 = (e & 31) * 4;
        float4 v = *(const float4*)&src[(size_t)(row0 + lr)*LAT + d4];
        *(float4*)&rsm[lr*132 + d4] = v;
    }
    const float* cbq = cb_all + (size_t)qi * KCB * LAT;
    float bestv[8], secv[8]; int besti[8];
    #pragma unroll
    for (int rr = 0; rr < 8; rr++) { bestv[rr] = 3.4e38f; secv[rr] = 3.4e38f; besti[rr] = 0; }

    for (int cc = 0; cc < 8; cc++) {
        __syncthreads();
        for (int e = tid; e < 128*32; e += 256) {
            int k = e >> 5, d4 = (e & 31) * 4;
            float4 v = *(const float4*)&cbq[(size_t)(cc*128 + k)*LAT + d4];
            *(float4*)&csm[k*132 + d4] = v;
        }
        if (tid < 128) nsm[tid] = g_cbn[qi*KCB + cc*128 + tid];
        __syncthreads();
        float acc[8][4];
        #pragma unroll
        for (int rr = 0; rr < 8; rr++)
            #pragma unroll
            for (int c = 0; c < 4; c++) acc[rr][c] = 0.f;
        #pragma unroll 2
        for (int d = 0; d < 128; d += 4) {
            float4 cv[4];
            #pragma unroll
            for (int c = 0; c < 4; c++) cv[c] = *(const float4*)&csm[(lane*4 + c)*132 + d];
            #pragma unroll
            for (int rr = 0; rr < 8; rr++) {
                float4 rv = *(const float4*)&rsm[(w*8 + rr)*132 + d];
                #pragma unroll
                for (int c = 0; c < 4; c++) {
                    acc[rr][c] += rv.x*cv[c].x + rv.y*cv[c].y + rv.z*cv[c].z + rv.w*cv[c].w;
                }
            }
        }
        #pragma unroll
        for (int rr = 0; rr < 8; rr++) {
            #pragma unroll
            for (int c = 0; c < 4; c++) {
                float dist = nsm[lane*4 + c] - 2.0f * acc[rr][c];
                int idx = cc*128 + lane*4 + c;
                if (dist < bestv[rr]) { secv[rr] = bestv[rr]; bestv[rr] = dist; besti[rr] = idx; }
                else if (dist < secv[rr]) { secv[rr] = dist; }
            }
        }
    }

    double dq_local = 0.0;
    for (int rr = 0; rr < 8; rr++) {
        float v1 = bestv[rr]; int i1 = besti[rr]; float v2 = secv[rr];
        #pragma unroll
        for (int off = 16; off > 0; off >>= 1) {
            float ov1 = __shfl_xor_sync(0xffffffffu, v1, off);
            int   oi1 = __shfl_xor_sync(0xffffffffu, i1, off);
            float ov2 = __shfl_xor_sync(0xffffffffu, v2, off);
            if (ov1 < v1 || (ov1 == v1 && oi1 < i1)) {
                v2 = fminf(v1, ov2);
                v1 = ov1; i1 = oi1;
            } else {
                v2 = fminf(v2, ov1);
            }
        }
        int ix = i1;
        int rloc = w*8 + rr;
        if (v2 - v1 < RESCORE_TAU) {
            double bd = 1e300; int bi = 0x7fffffff;
            for (int kk = 0; kk < 32; kk++) {
                int k = kk*32 + lane;
                const float* cr = cbq + (size_t)k * LAT;
                double s = 0.0;
                for (int d = 0; d < 128; d++) {
                    double cd = (double)cr[d];
                    double rd = (double)rsm[rloc*132 + d];
                    s += cd*cd - 2.0*rd*cd;
                }
                if (s < bd || (s == bd && k < bi)) { bd = s; bi = k; }
            }
            #pragma unroll
            for (int off = 16; off > 0; off >>= 1) {
                double ob = __shfl_xor_sync(0xffffffffu, bd, off);
                int    oi = __shfl_xor_sync(0xffffffffu, bi, off);
                if (ob < bd || (ob == bd && oi < bi)) { bd = ob; bi = oi; }
            }
            ix = bi;
        }

        int r = row0 + rloc;
        const float* q = cbq + (size_t)ix * LAT;
        float4 qv = *(const float4*)&q[lane*4];
        float4 rv = *(const float4*)&rsm[rloc*132 + lane*4];
        double r2 = (double)rv.x*rv.x + (double)rv.y*rv.y + (double)rv.z*rv.z + (double)rv.w*rv.w;
        double q2 = (double)qv.x*qv.x + (double)qv.y*qv.y + (double)qv.z*qv.z + (double)qv.w*qv.w;
        double rq = (double)rv.x*qv.x + (double)rv.y*qv.y + (double)rv.z*qv.z + (double)rv.w*qv.w;
        double dxd = (double)qv.x - rv.x, dyd = (double)qv.y - rv.y;
        double dzd = (double)qv.z - rv.z, dwd = (double)qv.w - rv.w;
        double dq = dxd*dxd + dyd*dyd + dzd*dzd + dwd*dwd;
        #pragma unroll
        for (int off = 16; off > 0; off >>= 1) {
            r2 += __shfl_xor_sync(0xffffffffu, r2, off);
            q2 += __shfl_xor_sync(0xffffffffu, q2, off);
            rq += __shfl_xor_sync(0xffffffffu, rq, off);
            dq += __shfl_xor_sync(0xffffffffu, dq, off);
        }
        double ns = sqrt(r2), nt = sqrt(q2);
        double ins = 1.0 / (ns + 1e-12), intq = 1.0 / (nt + 1e-12);
        double ru = r2 * ins;
        double ss2 = r2*ins*ins + 2.0*rq*ins*intq + q2*intq*intq;
        double wn = sqrt(ss2);
        double iw = 1.0 / (wn + 1e-12);
        double rs = ru + rq * intq;
        double rw = rs * iw;
        double scale = nt * ins;
        float4 qrf;
        {
            double sx = (double)rv.x*ins + (double)qv.x*intq;
            double sy = (double)rv.y*ins + (double)qv.y*intq;
            double sz = (double)rv.z*ins + (double)qv.z*intq;
            double sw = (double)rv.w*ins + (double)qv.w*intq;
            qrf.x = (float)(((double)rv.x - 2.0*rw*(sx*iw) + 2.0*ru*((double)qv.x*intq)) * scale);
            qrf.y = (float)(((double)rv.y - 2.0*rw*(sy*iw) + 2.0*ru*((double)qv.y*intq)) * scale);
            qrf.z = (float)(((double)rv.z - 2.0*rw*(sz*iw) + 2.0*ru*((double)qv.z*intq)) * scale);
            qrf.w = (float)(((double)rv.w - 2.0*rw*(sw*iw) + 2.0*ru*((double)qv.w*intq)) * scale);
        }
        size_t base = (size_t)r * LAT + lane*4;
        if (qi == 0) {
            *(float4*)&g_qout[base] = qrf;
        } else {
            float4 old = *(const float4*)&g_qout[base];
            old.x += qrf.x; old.y += qrf.y; old.z += qrf.z; old.w += qrf.w;
            *(float4*)&g_qout[base] = old;
        }
        if (qi < 3) {
            float4 nr = make_float4(rv.x - qrf.x, rv.y - qrf.y, rv.z - qrf.z, rv.w - qrf.w);
            *(float4*)&g_res[base] = nr;
        }
        if (lane == 0) {
            g_codes[r*NQ + qi] = ix;
            dq_local += dq;
        }
    }
    if (lane == 0) atomicAdd(&g_acc[qi], dq_local);
}

// ---------------- smooth loss ----------------
__global__ void k_smooth() {
    int idx = blockIdx.x * 256 + threadIdx.x;
    int cnt = 0;
    if (idx < BB * (TT - 1)) {
        int b = idx / (TT - 1), t = idx % (TT - 1);
        int a = g_codes[(b*TT + t)*NQ + 0];
        int c = g_codes[(b*TT + t + 1)*NQ + 0];
        cnt = (a != c) ? 1 : 0;
    }
    __shared__ int red[256];
    red[threadIdx.x] = cnt;
    __syncthreads();
    for (int s = 128; s > 0; s >>= 1) {
        if (threadIdx.x < s) red[threadIdx.x] += red[threadIdx.x + s];
        __syncthreads();
    }
    if (threadIdx.x == 0 && red[0]) atomicAdd(&g_acc[4], (double)red[0]);
}

// ---------------- fused decoder (unchanged) ----------------
__global__ __launch_bounds__(256) void k_dec(const float* __restrict__ b1,
                                             const float* __restrict__ b2) {
    extern __shared__ float sm[];
    float* insm = sm;
    float* hsm  = sm + 8*660;
    float* red  = hsm + 8*2560;
    int tid = threadIdx.x;
    int g0 = blockIdx.x * 8;

    for (int e = tid; e < 8*660; e += 256) {
        int ch = e / 660, rem = e % 660;
        int c = rem / 5, l = rem % 5;
        int g = g0 + ch;
        int b = g / COUNT_DEC, n = g % COUNT_DEC;
        int t = n*5 + l;
        float v;
        if (c < 128) v = g_qout[((size_t)b*TT + t)*LAT + c];
        else         v = (float)g_codes[(b*TT + t)*NQ + (c - 128)];
        insm[ch*660 + c*5 + l] = v;
    }
    __syncthreads();

    for (int op = 0; op < 2; op++) {
        int o = tid + op*256;
        float acc[8][5];
        float bbv = b1[o];
        #pragma unroll
        for (int ch = 0; ch < 8; ch++)
            #pragma unroll
            for (int l = 0; l < 5; l++) acc[ch][l] = bbv;
        for (int c = 0; c < 132; c++) {
            float inr[8][5];
            #pragma unroll
            for (int ch = 0; ch < 8; ch++)
                #pragma unroll
                for (int l = 0; l < 5; l++) inr[ch][l] = insm[ch*660 + c*5 + l];
            #pragma unroll
            for (int j = 0; j < 5; j++) {
                float wv = g_w1t[(c*5 + j)*512 + o];
                #pragma unroll
                for (int l = 0; l < 5; l++) {
                    int p = l + j - 2;
                    if (p >= 0 && p < 5) {
                        #pragma unroll
                        for (int ch = 0; ch < 8; ch++) acc[ch][l] += wv * inr[ch][p];
                    }
                }
            }
        }
        #pragma unroll
        for (int ch = 0; ch < 8; ch++)
            #pragma unroll
            for (int l = 0; l < 5; l++)
                hsm[ch*2560 + o*5 + l] = fmaxf(acc[ch][l], 0.f);
    }
    __syncthreads();

    int o2 = tid & 127, gp = tid >> 7;
    float acc2[4][5];
    float bb2 = b2[o2];
    #pragma unroll
    for (int cc = 0; cc < 4; cc++)
        #pragma unroll
        for (int l = 0; l < 5; l++) acc2[cc][l] = bb2;
    for (int c = 0; c < 512; c++) {
        float hr[4][5];
        #pragma unroll
        for (int cc = 0; cc < 4; cc++)
            #pragma unroll
            for (int l = 0; l < 5; l++) hr[cc][l] = hsm[(gp*4 + cc)*2560 + c*5 + l];
        #pragma unroll
        for (int j = 0; j < 3; j++) {
            float wv = g_w2t[(c*3 + j)*128 + o2];
            #pragma unroll
            for (int l = 0; l < 5; l++) {
                int p = l + j - 1;
                if (p >= 0 && p < 5) {
                    #pragma unroll
                    for (int cc = 0; cc < 4; cc++) acc2[cc][l] += wv * hr[cc][p];
                }
            }
        }
    }
    float lsum = 0.f;
    #pragma unroll
    for (int cc = 0; cc < 4; cc++) {
        int g = g0 + gp*4 + cc;
        int b = g / COUNT_DEC, n = g % COUNT_DEC;
        #pragma unroll
        for (int l = 0; l < 5; l++) {
            int t = (n + 1)*5 + l;
            float d = acc2[cc][l] - g_qout[((size_t)b*TT + t)*LAT + o2];
            lsum += d*d;
        }
    }
    red[tid] = lsum;
    __syncthreads();
    for (int s = 128; s > 0; s >>= 1) {
        if (tid < s) red[tid] += red[tid + s];
        __syncthreads();
    }
    if (tid == 0) atomicAdd(&g_acc[5], (double)red[0]);
}

// ---------------- outputs ----------------
__global__ void k_codes_out(float* __restrict__ out, int out_size) {
    int i = blockIdx.x * 256 + threadIdx.x;
    if (i < BB*TT*NQ && i < out_size) out[i] = (float)g_codes[i];
}
__global__ void k_final(float* __restrict__ out, int out_size) {
    if (threadIdx.x != 0 || blockIdx.x != 0) return;
    double nv = (double)BB * TT * LAT;
    double vq = (g_acc[0]/nv + g_acc[1]/nv + g_acc[2]/nv + g_acc[3]/nv) / 4.0;
    double recon = g_acc[5] / ((double)NCHUNKS * LAT * 5);
    double smooth = g_acc[4] / ((double)BB * (TT - 1));
    double loss = recon * 1.0 + vq * 1.0 + smooth * 0.1;
    int base = BB*TT*NQ;
    if (base + 0 < out_size) out[base + 0] = (float)loss;
    if (base + 1 < out_size) out[base + 1] = (float)recon;
    if (base + 2 < out_size) out[base + 2] = (float)vq;
    if (base + 3 < out_size) out[base + 3] = (float)smooth;
}

// ---------------- launch (index 3 = k_enc2a_hmma for ncu) ----------------
extern "C" void kernel_launch(void* const* d_in, const int* in_sizes, int n_in,
                              void* d_out, int out_size) {
    const float* traj = (const float*)d_in[0];
    const float* e1w  = (const float*)d_in[2];
    const float* e1b  = (const float*)d_in[3];
    const float* e2aw = (const float*)d_in[4];
    const float* e2ab = (const float*)d_in[5];
    const float* e2bw = (const float*)d_in[6];
    const float* e2bb = (const float*)d_in[7];
    const float* d1w  = (const float*)d_in[8];
    const float* d1b  = (const float*)d_in[9];
    const float* d2w  = (const float*)d_in[10];
    const float* d2b  = (const float*)d_in[11];
    const float* cb   = (const float*)d_in[12];
    float* out = (float*)d_out;

    const int VQ_SMEM  = (64*132 + 128*132 + 128) * 4;
    const int DEC_SMEM = (8*660 + 8*2560 + 256) * 4;
    const int CB_SMEM  = (2*(8*7*132) + 2*8*40) * 4;
    const int HM_SMEM  = 45056 + 16*68*4;   // 49,408 B
    cudaFuncSetAttribute(k_vq,  cudaFuncAttributeMaxDynamicSharedMemorySize, VQ_SMEM);
    cudaFuncSetAttribute(k_dec, cudaFuncAttributeMaxDynamicSharedMemorySize, DEC_SMEM);
    cudaFuncSetAttribute((const void*)k_conv3<7, false, true, false, 1>,
                         cudaFuncAttributeMaxDynamicSharedMemorySize, CB_SMEM);
    cudaFuncSetAttribute(k_enc2a_hmma,
                         cudaFuncAttributeMaxDynamicSharedMemorySize, HM_SMEM);

    void *p_z3 = nullptr, *p_ze = nullptr, *p_wb = nullptr, *p_wh = nullptr;
    cudaGetSymbolAddress(&p_z3, g_z3);
    cudaGetSymbolAddress(&p_ze, g_ze);
    cudaGetSymbolAddress(&p_wb, g_wb);
    cudaGetSymbolAddress(&p_wh, g_wh);

    k_zero_acc<<<1, 32>>>();                                               // 0
    k_enc1<<<dim3(TN/16, BB), 256>>>(traj, e1w, e1b);                      // 1
    k_wprep2<<<(4*32*128*88 + 255)/256, 256>>>(e2aw);                      // 2
    // enc2a: HMMA bf16 2-limb implicit GEMM                               // 3 <- ncu target
    k_enc2a_hmma<<<dim3(125, 4, BB), 256, HM_SMEM>>>(
        (const __nv_bfloat16*)p_wh, e2ab);
    k_wstage<<<(1*64*8*7*128)/256, 256>>>(e2bw, (float*)p_wb, 7, 1);       // 4
    // enc2b: 512->128, K=7, transposed out (B,T,128), scalar path         // 5
    k_conv3<7, false, true, false, 1><<<dim3(TT/32, 1, BB), 256, CB_SMEM>>>(
        (const float*)p_z3, (const float*)p_wb, e2bb, (float*)p_ze);
    k_tw1<<<(512*660 + 255)/256, 256>>>(d1w);                              // 6
    k_tw2<<<(128*1536 + 255)/256, 256>>>(d2w);                             // 7
    k_cbnorm<<<(NQ*KCB)/256, 256>>>(cb);                                   // 8
    for (int qi = 0; qi < NQ; qi++) {
        k_vq<<<(BB*TT)/64, 256, VQ_SMEM>>>(cb, qi);                        // 9-12
    }
    k_smooth<<<(BB*(TT-1) + 255)/256, 256>>>();                            // 13
    k_dec<<<NCHUNKS/8, 256, DEC_SMEM>>>(d1b, d2b);                         // 14
    k_codes_out<<<(BB*TT*NQ)/256, 256>>>(out, out_size);                   // 15
    k_final<<<1, 32>>>(out, out_size);                                     // 16
}